// round 1
// baseline (speedup 1.0000x reference)
#include <cuda_runtime.h>
#include <math.h>
#include <float.h>

// Problem constants
#define B_DIM 32
#define C_DIM 9
#define T_DIM 4096
#define NROWS (B_DIM * T_DIM)          // 131072
#define NCODES 512
#define CODE_DIM 64
#define HALF_DIM 32
#define PDIM 12                        // 11 feature dims + bias

#define Q_OFF 0
#define IDX_OFF (NROWS * CODE_DIM)     // 8388608
#define PH_OFF (IDX_OFF + NROWS)       // 8519680

// Scratch (no cudaMalloc allowed): per-channel phases + precomputed code tables
__device__ float  g_phase_scratch[B_DIM * C_DIM * T_DIM];
__device__ float  g_p32[NCODES * PDIM];
__device__ double g_p64[NCODES * PDIM];

// ---------------------------------------------------------------------------
// Kernel 1: analytic-signal phase via in-smem radix-2 FFT (4096 pts)
// one block per (b, c)
// ---------------------------------------------------------------------------
__device__ __forceinline__ int brev12(int i) {
    return (int)(__brev((unsigned)i) >> 20);
}

__device__ void fft4096_stages(float2* buf, const float2* tw, int tid) {
    #pragma unroll 1
    for (int s = 1; s <= 12; s++) {
        int half = 1 << (s - 1);
        int step = 4096 >> s;  // twiddle stride: 4096/m
        #pragma unroll
        for (int q = tid; q < 2048; q += 512) {
            int j   = q & (half - 1);
            int grp = q >> (s - 1);
            int pos = (grp << s) + j;
            float2 w = tw[j * step];
            float2 a = buf[pos];
            float2 b = buf[pos + half];
            float tr = w.x * b.x - w.y * b.y;
            float ti = w.x * b.y + w.y * b.x;
            buf[pos]        = make_float2(a.x + tr, a.y + ti);
            buf[pos + half] = make_float2(a.x - tr, a.y - ti);
        }
        __syncthreads();
    }
}

__global__ void phase_kernel(const float* __restrict__ imu) {
    extern __shared__ float2 sm[];
    float2* buf = sm;          // 4096
    float2* tw  = sm + 4096;   // 2048

    int tid = threadIdx.x;     // 512 threads
    int bc  = blockIdx.x;      // 0..287  (= b*9 + c)

    // Twiddle table W[k] = exp(-2*pi*i*k/4096), computed in double for accuracy
    for (int k = tid; k < 2048; k += 512) {
        double a = -2.0 * M_PI * (double)k / 4096.0;
        tw[k] = make_float2((float)cos(a), (float)sin(a));
    }

    const float* x = imu + (size_t)bc * T_DIM;
    for (int i = tid; i < 4096; i += 512) {
        buf[brev12(i)] = make_float2(x[i], 0.0f);
    }
    __syncthreads();

    // Forward FFT
    fft4096_stages(buf, tw, tid);

    // Multiply by Hilbert multiplier h and conjugate (prep for ifft-via-conj)
    for (int i = tid; i < 4096; i += 512) {
        float hm = (i == 0 || i == 2048) ? 1.0f : (i < 2048 ? 2.0f : 0.0f);
        float2 v = buf[i];
        buf[i] = make_float2(v.x * hm, -v.y * hm);
    }
    __syncthreads();

    // Bit-reverse permute in place
    for (int i = tid; i < 4096; i += 512) {
        int r = brev12(i);
        if (i < r) { float2 a = buf[i]; buf[i] = buf[r]; buf[r] = a; }
    }
    __syncthreads();

    // Second FFT; analytic = conj(result)/N, scale cancels in atan2
    fft4096_stages(buf, tw, tid);

    float* dst = g_phase_scratch + (size_t)bc * T_DIM;
    for (int i = tid; i < 4096; i += 512) {
        float2 z = buf[i];
        dst[i] = atan2f(-z.y, z.x);
    }
}

// ---------------------------------------------------------------------------
// Kernel 2: precompute per-code projected 12-dim tables (fp64 + fp32 copies)
// p[0..6] = u+v, p[7]=u7, p[8]=u8, p[9]=v7, p[10]=v8, p[11]=bias
// where u = W_mag^T c_mag (9), v = W_phase^T c_ph (9),
//       bias = b_mag.c_mag + b_phase.c_ph - 0.5*||c||^2
// score s_k = g . p_k[0:11] + p_k[11],  g=[imu0..8, cos(ph), sin(ph)]
// argmin d2 == argmax s
// one block per code, 32 lanes split the 32-dim halves, warp-reduce
// ---------------------------------------------------------------------------
__device__ __forceinline__ double warp_sum_d(double v) {
    #pragma unroll
    for (int m = 16; m > 0; m >>= 1) {
        v += __shfl_xor_sync(0xFFFFFFFFu, v, m);
    }
    return v;
}

__global__ void precompute_kernel(const float* __restrict__ W_mag,
                                  const float* __restrict__ b_mag,
                                  const float* __restrict__ W_phase,
                                  const float* __restrict__ b_phase,
                                  const float* __restrict__ codebook) {
    int k = blockIdx.x;      // code
    int d = threadIdx.x;     // 0..31 (dim within each half)
    const float* c = codebook + k * CODE_DIM;

    double cm = (double)c[d];
    double cp = (double)c[HALF_DIM + d];

    double u[9], v[9];
    #pragma unroll
    for (int i = 0; i < 9; i++) {
        u[i] = (double)W_mag[d * 9 + i] * cm;
        v[i] = (double)W_phase[d * 9 + i] * cp;
    }
    double w = (double)b_mag[d] * cm + (double)b_phase[d] * cp
             - 0.5 * (cm * cm + cp * cp);

    double p[PDIM];
    #pragma unroll
    for (int i = 0; i < 7; i++) p[i] = warp_sum_d(u[i] + v[i]);
    p[7]  = warp_sum_d(u[7]);
    p[8]  = warp_sum_d(u[8]);
    p[9]  = warp_sum_d(v[7]);
    p[10] = warp_sum_d(v[8]);
    p[11] = warp_sum_d(w);

    if (d == 0) {
        #pragma unroll
        for (int i = 0; i < PDIM; i++) {
            g_p64[k * PDIM + i] = p[i];
            g_p32[k * PDIM + i] = (float)p[i];
        }
    }
}

// ---------------------------------------------------------------------------
// Kernel 3: per-row score argmax + gather + outputs
// one thread per row; 512-code loop over smem p-table (warp-broadcast LDS)
// ---------------------------------------------------------------------------
__global__ void __launch_bounds__(128) quantize_kernel(
    const float* __restrict__ imu,
    const float* __restrict__ codebook,
    float* __restrict__ out) {

    __shared__ float sp[NCODES * PDIM];   // 24 KB
    int tid = threadIdx.x;
    for (int i = tid; i < NCODES * PDIM; i += 128) sp[i] = g_p32[i];
    __syncthreads();

    int row = blockIdx.x * 128 + tid;     // grid covers exactly NROWS
    int b = row >> 12;
    int t = row & 4095;

    // mean phase over channels (sequential, deterministic)
    const float* phbase = g_phase_scratch + (size_t)(b * C_DIM) * T_DIM + t;
    float ph = 0.0f;
    #pragma unroll
    for (int c = 0; c < 9; c++) ph += phbase[(size_t)c * T_DIM];
    ph *= (1.0f / 9.0f);

    // 11-dim raw feature
    float g[11];
    const float* ib = imu + (size_t)(b * C_DIM) * T_DIM + t;
    #pragma unroll
    for (int c = 0; c < 9; c++) g[c] = ib[(size_t)c * T_DIM];
    g[9]  = cosf(ph);
    g[10] = sinf(ph);

    float best  = -FLT_MAX;
    float best2 = -FLT_MAX;
    int   bidx  = 0;

    #pragma unroll 4
    for (int j = 0; j < NCODES; j++) {
        const float4* pr = (const float4*)(sp + j * PDIM);
        float4 p0 = pr[0];
        float4 p1 = pr[1];
        float4 p2 = pr[2];
        float s = p2.w;
        s = fmaf(g[0],  p0.x, s);
        s = fmaf(g[1],  p0.y, s);
        s = fmaf(g[2],  p0.z, s);
        s = fmaf(g[3],  p0.w, s);
        s = fmaf(g[4],  p1.x, s);
        s = fmaf(g[5],  p1.y, s);
        s = fmaf(g[6],  p1.z, s);
        s = fmaf(g[7],  p1.w, s);
        s = fmaf(g[8],  p2.x, s);
        s = fmaf(g[9],  p2.y, s);
        s = fmaf(g[10], p2.z, s);
        if (s > best) {
            best2 = best;
            best = s;
            bidx = j;                 // strict > keeps lowest index (first min)
        } else if (s > best2) {
            best2 = s;
        }
    }

    // Near-tie: re-rank exactly in fp64 (rare path; keeps argmin == true argmin)
    if (best - best2 < 1e-3f) {
        double gd[11];
        #pragma unroll
        for (int i = 0; i < 11; i++) gd[i] = (double)g[i];
        double bd = -1.0e300;
        int bi = 0;
        for (int j = 0; j < NCODES; j++) {
            const double* pr = g_p64 + j * PDIM;
            double s = pr[11];
            #pragma unroll
            for (int i = 0; i < 11; i++) s += gd[i] * pr[i];
            if (s > bd) { bd = s; bi = j; }
        }
        bidx = bi;
    }

    // outputs: quantized (gather), index, phase
    const float4* cb = (const float4*)(codebook + (size_t)bidx * CODE_DIM);
    float4* oq = (float4*)(out + (size_t)row * CODE_DIM);
    #pragma unroll
    for (int i = 0; i < CODE_DIM / 4; i++) oq[i] = cb[i];
    out[IDX_OFF + row] = (float)bidx;
    out[PH_OFF + row] = ph;
}

// ---------------------------------------------------------------------------
extern "C" void kernel_launch(void* const* d_in, const int* in_sizes, int n_in,
                              void* d_out, int out_size) {
    const float* imu      = (const float*)d_in[0];
    const float* W_mag    = (const float*)d_in[1];
    const float* b_mag    = (const float*)d_in[2];
    const float* W_phase  = (const float*)d_in[3];
    const float* b_phase  = (const float*)d_in[4];
    const float* codebook = (const float*)d_in[5];
    float* out = (float*)d_out;

    // 48KB dynamic smem: 4096 + 2048 float2
    phase_kernel<<<B_DIM * C_DIM, 512, 6144 * sizeof(float2)>>>(imu);
    precompute_kernel<<<NCODES, 32>>>(W_mag, b_mag, W_phase, b_phase, codebook);
    quantize_kernel<<<NROWS / 128, 128>>>(imu, codebook, out);
}

// round 2
// speedup vs baseline: 2.7456x; 2.7456x over previous
#include <cuda_runtime.h>
#include <math.h>
#include <float.h>

// Problem constants
#define B_DIM 32
#define C_DIM 9
#define T_DIM 4096
#define NROWS (B_DIM * T_DIM)          // 131072
#define NCODES 512
#define CODE_DIM 64
#define HALF_DIM 32
#define PDIM 12                        // 11 feature dims + bias

#define Q_OFF 0
#define IDX_OFF (NROWS * CODE_DIM)     // 8388608
#define PH_OFF (IDX_OFF + NROWS)       // 8519680

// Scratch (no cudaMalloc allowed)
__device__ float  g_phase_scratch[B_DIM * C_DIM * T_DIM];
__device__ float  g_p32[NCODES * PDIM];
__device__ double g_p64[NCODES * PDIM];

// ---------------------------------------------------------------------------
// Kernel 1: analytic-signal phase via in-smem radix-2 FFT (4096 pts)
// one block per (b, c)
// ---------------------------------------------------------------------------
__device__ __forceinline__ int brev12(int i) {
    return (int)(__brev((unsigned)i) >> 20);
}

__device__ void fft4096_stages(float2* buf, const float2* tw, int tid) {
    #pragma unroll 1
    for (int s = 1; s <= 12; s++) {
        int half = 1 << (s - 1);
        int step = 4096 >> s;  // twiddle stride
        #pragma unroll
        for (int q = tid; q < 2048; q += 512) {
            int j   = q & (half - 1);
            int grp = q >> (s - 1);
            int pos = (grp << s) + j;
            float2 w = tw[j * step];
            float2 a = buf[pos];
            float2 b = buf[pos + half];
            float tr = w.x * b.x - w.y * b.y;
            float ti = w.x * b.y + w.y * b.x;
            buf[pos]        = make_float2(a.x + tr, a.y + ti);
            buf[pos + half] = make_float2(a.x - tr, a.y - ti);
        }
        __syncthreads();
    }
}

__global__ void phase_kernel(const float* __restrict__ imu) {
    extern __shared__ float2 sm[];
    float2* buf = sm;          // 4096
    float2* tw  = sm + 4096;   // 2048

    int tid = threadIdx.x;     // 512 threads
    int bc  = blockIdx.x;      // 0..287  (= b*9 + c)

    // Twiddle table W[k] = exp(-2*pi*i*k/4096) via float sincospi
    // angle = pi * (-k/2048); k/2048 is exact in fp32 -> high accuracy, cheap
    for (int k = tid; k < 2048; k += 512) {
        float sv, cv;
        sincospif(-(float)k * (1.0f / 2048.0f), &sv, &cv);
        tw[k] = make_float2(cv, sv);
    }

    const float* x = imu + (size_t)bc * T_DIM;
    for (int i = tid; i < 4096; i += 512) {
        buf[brev12(i)] = make_float2(x[i], 0.0f);
    }
    __syncthreads();

    // Forward FFT
    fft4096_stages(buf, tw, tid);

    // Hilbert multiplier + conjugate (prep for ifft-via-conj trick)
    for (int i = tid; i < 4096; i += 512) {
        float hm = (i == 0 || i == 2048) ? 1.0f : (i < 2048 ? 2.0f : 0.0f);
        float2 v = buf[i];
        buf[i] = make_float2(v.x * hm, -v.y * hm);
    }
    __syncthreads();

    // Bit-reverse permute in place
    for (int i = tid; i < 4096; i += 512) {
        int r = brev12(i);
        if (i < r) { float2 a = buf[i]; buf[i] = buf[r]; buf[r] = a; }
    }
    __syncthreads();

    // Second FFT; analytic = conj(result)/N, scale cancels in atan2
    fft4096_stages(buf, tw, tid);

    float* dst = g_phase_scratch + (size_t)bc * T_DIM;
    for (int i = tid; i < 4096; i += 512) {
        float2 z = buf[i];
        dst[i] = atan2f(-z.y, z.x);
    }
}

// ---------------------------------------------------------------------------
// Kernel 2: precompute per-code projected 12-dim tables (fp64 + fp32 copies)
// score s_k = g . p_k[0:11] + p_k[11],  g=[imu0..8, cos(ph), sin(ph)]
// argmin d2 == argmax s
// ---------------------------------------------------------------------------
__device__ __forceinline__ double warp_sum_d(double v) {
    #pragma unroll
    for (int m = 16; m > 0; m >>= 1) {
        v += __shfl_xor_sync(0xFFFFFFFFu, v, m);
    }
    return v;
}

__global__ void precompute_kernel(const float* __restrict__ W_mag,
                                  const float* __restrict__ b_mag,
                                  const float* __restrict__ W_phase,
                                  const float* __restrict__ b_phase,
                                  const float* __restrict__ codebook) {
    int k = blockIdx.x;      // code
    int d = threadIdx.x;     // 0..31 (dim within each half)
    const float* c = codebook + k * CODE_DIM;

    double cm = (double)c[d];
    double cp = (double)c[HALF_DIM + d];

    double u[9], v[9];
    #pragma unroll
    for (int i = 0; i < 9; i++) {
        u[i] = (double)W_mag[d * 9 + i] * cm;
        v[i] = (double)W_phase[d * 9 + i] * cp;
    }
    double w = (double)b_mag[d] * cm + (double)b_phase[d] * cp
             - 0.5 * (cm * cm + cp * cp);

    double p[PDIM];
    #pragma unroll
    for (int i = 0; i < 7; i++) p[i] = warp_sum_d(u[i] + v[i]);
    p[7]  = warp_sum_d(u[7]);
    p[8]  = warp_sum_d(u[8]);
    p[9]  = warp_sum_d(v[7]);
    p[10] = warp_sum_d(v[8]);
    p[11] = warp_sum_d(w);

    if (d == 0) {
        #pragma unroll
        for (int i = 0; i < PDIM; i++) {
            g_p64[k * PDIM + i] = p[i];
            g_p32[k * PDIM + i] = (float)p[i];
        }
    }
}

// ---------------------------------------------------------------------------
// Kernel 3: per-row score argmax + gather + outputs
// ---------------------------------------------------------------------------
__device__ __forceinline__ float score12(const float* __restrict__ sp, int j,
                                         const float* __restrict__ g) {
    const float4* pr = (const float4*)(sp + j * PDIM);
    float4 p0 = pr[0];
    float4 p1 = pr[1];
    float4 p2 = pr[2];
    float s = p2.w;
    s = fmaf(g[0],  p0.x, s);
    s = fmaf(g[1],  p0.y, s);
    s = fmaf(g[2],  p0.z, s);
    s = fmaf(g[3],  p0.w, s);
    s = fmaf(g[4],  p1.x, s);
    s = fmaf(g[5],  p1.y, s);
    s = fmaf(g[6],  p1.z, s);
    s = fmaf(g[7],  p1.w, s);
    s = fmaf(g[8],  p2.x, s);
    s = fmaf(g[9],  p2.y, s);
    s = fmaf(g[10], p2.z, s);
    return s;
}

__global__ void __launch_bounds__(128) quantize_kernel(
    const float* __restrict__ imu,
    const float* __restrict__ codebook,
    float* __restrict__ out) {

    __shared__ float sp[NCODES * PDIM];   // 24 KB
    int tid = threadIdx.x;
    for (int i = tid; i < NCODES * PDIM; i += 128) sp[i] = g_p32[i];
    __syncthreads();

    int row = blockIdx.x * 128 + tid;     // grid covers exactly NROWS
    int b = row >> 12;
    int t = row & 4095;

    // mean phase over channels (sequential, deterministic)
    const float* phbase = g_phase_scratch + (size_t)(b * C_DIM) * T_DIM + t;
    float ph = 0.0f;
    #pragma unroll
    for (int c = 0; c < 9; c++) ph += phbase[(size_t)c * T_DIM];
    ph *= (1.0f / 9.0f);

    // 11-dim raw feature
    float g[11];
    const float* ib = imu + (size_t)(b * C_DIM) * T_DIM + t;
    #pragma unroll
    for (int c = 0; c < 9; c++) g[c] = ib[(size_t)c * T_DIM];
    g[9]  = cosf(ph);
    g[10] = sinf(ph);

    float best  = -FLT_MAX;
    float best2 = -FLT_MAX;
    int   bidx  = 0;

    #pragma unroll 4
    for (int j = 0; j < NCODES; j++) {
        float s = score12(sp, j, g);
        if (s > best) {
            best2 = best;
            best = s;
            bidx = j;                 // strict > keeps lowest index (first min)
        } else if (s > best2) {
            best2 = s;
        }
    }

    // Near-tie: collect candidates within window, fp64-rerank ONLY those.
    // (Keeps the exact-argmin guarantee without a 512x serial-DFMA tail.)
    if (best - best2 < 1e-3f) {
        int cand[8];
        int nc = 0;
        float thr = best - 2e-3f;
        #pragma unroll 4
        for (int j = 0; j < NCODES; j++) {
            float s = score12(sp, j, g);
            if (s >= thr && nc < 8) cand[nc++] = j;
        }
        double gd[11];
        #pragma unroll
        for (int i = 0; i < 11; i++) gd[i] = (double)g[i];
        double bd = -1.0e300;
        int bi = bidx;
        for (int m = 0; m < nc; m++) {
            int j = cand[m];
            const double* pr = g_p64 + j * PDIM;
            double s0 = pr[11];
            double s1 = 0.0;
            #pragma unroll
            for (int i = 0; i < 10; i += 2) {
                s0 += gd[i]     * pr[i];
                s1 += gd[i + 1] * pr[i + 1];
            }
            s0 += gd[10] * pr[10];
            double s = s0 + s1;
            if (s > bd) { bd = s; bi = j; }   // cand ascending -> lowest idx wins ties
        }
        bidx = bi;
    }

    // outputs: quantized (gather), index, phase
    const float4* cb = (const float4*)(codebook + (size_t)bidx * CODE_DIM);
    float4* oq = (float4*)(out + (size_t)row * CODE_DIM);
    #pragma unroll
    for (int i = 0; i < CODE_DIM / 4; i++) oq[i] = cb[i];
    out[IDX_OFF + row] = (float)bidx;
    out[PH_OFF + row] = ph;
}

// ---------------------------------------------------------------------------
extern "C" void kernel_launch(void* const* d_in, const int* in_sizes, int n_in,
                              void* d_out, int out_size) {
    const float* imu      = (const float*)d_in[0];
    const float* W_mag    = (const float*)d_in[1];
    const float* b_mag    = (const float*)d_in[2];
    const float* W_phase  = (const float*)d_in[3];
    const float* b_phase  = (const float*)d_in[4];
    const float* codebook = (const float*)d_in[5];
    float* out = (float*)d_out;

    // 48KB dynamic smem: 4096 + 2048 float2
    phase_kernel<<<B_DIM * C_DIM, 512, 6144 * sizeof(float2)>>>(imu);
    precompute_kernel<<<NCODES, 32>>>(W_mag, b_mag, W_phase, b_phase, codebook);
    quantize_kernel<<<NROWS / 128, 128>>>(imu, codebook, out);
}

// round 4
// speedup vs baseline: 3.2955x; 1.2003x over previous
#include <cuda_runtime.h>
#include <math.h>
#include <float.h>

// Problem constants
#define B_DIM 32
#define C_DIM 9
#define T_DIM 4096
#define NROWS (B_DIM * T_DIM)          // 131072
#define NCODES 512
#define CODE_DIM 64
#define HALF_DIM 32
#define PDIM 12                        // 11 feature dims + bias
#define NPAIRS (NCODES / 2)            // 256
#define PROW (PDIM * 2)                // 24 floats per pair row

#define IDX_OFF (NROWS * CODE_DIM)     // 8388608
#define PH_OFF (IDX_OFF + NROWS)       // 8519680

// Scratch (no cudaMalloc allowed)
__device__ float  g_phase_scratch[B_DIM * C_DIM * T_DIM];
__device__ float  g_p32[NPAIRS * PROW];     // pair-interleaved fp32 table
__device__ double g_p64[NCODES * PDIM];

// ---------------------------------------------------------------------------
// Kernel 1: analytic-signal phase via in-smem radix-4 FFT (4096 = 4^6 pts)
// one block per (b, c), 512 threads
// ---------------------------------------------------------------------------
__device__ __forceinline__ int digrev4(int i) {
    int r = 0;
    #pragma unroll
    for (int k = 0; k < 6; k++) { r = (r << 2) | (i & 3); i >>= 2; }
    return r;
}

__device__ __forceinline__ float2 cmul(float2 a, float2 b) {
    return make_float2(fmaf(a.x, b.x, -a.y * b.y), fmaf(a.x, b.y, a.y * b.x));
}

// tw[k] = W_4096^k = exp(-2*pi*i*k/4096), k in [0, 1024)
__device__ void fft4096_r4(float2* __restrict__ buf, const float2* __restrict__ tw,
                           int tid) {
    #pragma unroll 1
    for (int s = 0; s < 6; s++) {
        int quarter = 1 << (2 * s);      // L/4
        int rstep   = 1024 >> (2 * s);   // N/L
        #pragma unroll
        for (int q = tid; q < 1024; q += 512) {
            int j   = q & (quarter - 1);
            int grp = q >> (2 * s);
            int pos = grp * (quarter << 2) + j;

            float2 w1 = tw[j * rstep];
            float2 w2 = cmul(w1, w1);
            float2 w3 = cmul(w2, w1);

            float2 a0 = buf[pos];
            float2 a1 = cmul(buf[pos + quarter],     w1);
            float2 a2 = cmul(buf[pos + 2 * quarter], w2);
            float2 a3 = cmul(buf[pos + 3 * quarter], w3);

            float2 t0 = make_float2(a0.x + a2.x, a0.y + a2.y);
            float2 t1 = make_float2(a0.x - a2.x, a0.y - a2.y);
            float2 t2 = make_float2(a1.x + a3.x, a1.y + a3.y);
            float2 t3 = make_float2(a1.x - a3.x, a1.y - a3.y);

            buf[pos]               = make_float2(t0.x + t2.x, t0.y + t2.y);
            buf[pos + quarter]     = make_float2(t1.x + t3.y, t1.y - t3.x);  // t1 - i*t3
            buf[pos + 2 * quarter] = make_float2(t0.x - t2.x, t0.y - t2.y);
            buf[pos + 3 * quarter] = make_float2(t1.x - t3.y, t1.y + t3.x);  // t1 + i*t3
        }
        __syncthreads();
    }
}

__global__ void phase_kernel(const float* __restrict__ imu) {
    extern __shared__ float2 sm[];
    float2* buf = sm;          // 4096
    float2* tw  = sm + 4096;   // 1024

    int tid = threadIdx.x;     // 512 threads
    int bc  = blockIdx.x;      // 0..287  (= b*9 + c)

    for (int k = tid; k < 1024; k += 512) {
        float sv, cv;
        sincospif(-(float)k * (1.0f / 2048.0f), &sv, &cv);
        tw[k] = make_float2(cv, sv);
    }

    const float* x = imu + (size_t)bc * T_DIM;
    for (int i = tid; i < 4096; i += 512) {
        buf[digrev4(i)] = make_float2(x[i], 0.0f);
    }
    __syncthreads();

    // Forward FFT
    fft4096_r4(buf, tw, tid);

    // Hilbert multiplier + conjugate (prep for ifft-via-conj trick)
    for (int i = tid; i < 4096; i += 512) {
        float hm = (i == 0 || i == 2048) ? 1.0f : (i < 2048 ? 2.0f : 0.0f);
        float2 v = buf[i];
        buf[i] = make_float2(v.x * hm, -v.y * hm);
    }
    __syncthreads();

    // Digit-reverse permute in place (digrev4 is an involution)
    for (int i = tid; i < 4096; i += 512) {
        int r = digrev4(i);
        if (i < r) { float2 a = buf[i]; buf[i] = buf[r]; buf[r] = a; }
    }
    __syncthreads();

    // Second FFT; analytic = conj(result)/N, scale cancels in atan2
    fft4096_r4(buf, tw, tid);

    float* dst = g_phase_scratch + (size_t)bc * T_DIM;
    for (int i = tid; i < 4096; i += 512) {
        float2 z = buf[i];
        dst[i] = atan2f(-z.y, z.x);
    }
}

// ---------------------------------------------------------------------------
// Kernel 2: precompute per-code projected 12-dim tables (fp64 + fp32 copies)
// score s_k = g . p_k[0:11] + p_k[11],  g=[imu0..8, cos(ph), sin(ph)]
// argmin d2 == argmax s
// ---------------------------------------------------------------------------
__device__ __forceinline__ double warp_sum_d(double v) {
    #pragma unroll
    for (int m = 16; m > 0; m >>= 1) {
        v += __shfl_xor_sync(0xFFFFFFFFu, v, m);
    }
    return v;
}

__global__ void precompute_kernel(const float* __restrict__ W_mag,
                                  const float* __restrict__ b_mag,
                                  const float* __restrict__ W_phase,
                                  const float* __restrict__ b_phase,
                                  const float* __restrict__ codebook) {
    int k = blockIdx.x;      // code
    int d = threadIdx.x;     // 0..31 (dim within each half)
    const float* c = codebook + k * CODE_DIM;

    double cm = (double)c[d];
    double cp = (double)c[HALF_DIM + d];

    double u[9], v[9];
    #pragma unroll
    for (int i = 0; i < 9; i++) {
        u[i] = (double)W_mag[d * 9 + i] * cm;
        v[i] = (double)W_phase[d * 9 + i] * cp;
    }
    double w = (double)b_mag[d] * cm + (double)b_phase[d] * cp
             - 0.5 * (cm * cm + cp * cp);

    double p[PDIM];
    #pragma unroll
    for (int i = 0; i < 7; i++) p[i] = warp_sum_d(u[i] + v[i]);
    p[7]  = warp_sum_d(u[7]);
    p[8]  = warp_sum_d(u[8]);
    p[9]  = warp_sum_d(v[7]);
    p[10] = warp_sum_d(v[8]);
    p[11] = warp_sum_d(w);

    if (d == 0) {
        #pragma unroll
        for (int i = 0; i < PDIM; i++) {
            g_p64[k * PDIM + i] = p[i];
            // pair-interleaved fp32: [pair][dim][parity]
            g_p32[(k >> 1) * PROW + i * 2 + (k & 1)] = (float)p[i];
        }
    }
}

// ---------------------------------------------------------------------------
// Kernel 3: per-row score argmax via packed f32x2 FMA + gather + outputs
// ---------------------------------------------------------------------------
__device__ __forceinline__ unsigned long long pack2(float lo, float hi) {
    unsigned long long r;
    asm("mov.b64 %0, {%1, %2};" : "=l"(r) : "f"(lo), "f"(hi));
    return r;
}

__device__ __forceinline__ void unpack2(unsigned long long v, float& lo, float& hi) {
    asm("mov.b64 {%0, %1}, %2;" : "=f"(lo), "=f"(hi) : "l"(v));
}

__device__ __forceinline__ unsigned long long fma2(unsigned long long a,
                                                   unsigned long long b,
                                                   unsigned long long c) {
    unsigned long long d;
    asm("fma.rn.f32x2 %0, %1, %2, %3;" : "=l"(d) : "l"(a), "l"(b), "l"(c));
    return d;
}

// packed score for pair j: returns (score[2j], score[2j+1]) packed
__device__ __forceinline__ unsigned long long score_pair(
    const float* __restrict__ sp, int j, const unsigned long long* __restrict__ gp) {
    const ulonglong2* pr = (const ulonglong2*)(sp + j * PROW);
    ulonglong2 v0 = pr[0];   // dims 0,1
    ulonglong2 v1 = pr[1];   // dims 2,3
    ulonglong2 v2 = pr[2];   // dims 4,5
    ulonglong2 v3 = pr[3];   // dims 6,7
    ulonglong2 v4 = pr[4];   // dims 8,9
    ulonglong2 v5 = pr[5];   // dims 10,11(bias)
    unsigned long long acc = v5.y;                 // bias pair
    acc = fma2(gp[0],  v0.x, acc);
    acc = fma2(gp[1],  v0.y, acc);
    acc = fma2(gp[2],  v1.x, acc);
    acc = fma2(gp[3],  v1.y, acc);
    acc = fma2(gp[4],  v2.x, acc);
    acc = fma2(gp[5],  v2.y, acc);
    acc = fma2(gp[6],  v3.x, acc);
    acc = fma2(gp[7],  v3.y, acc);
    acc = fma2(gp[8],  v4.x, acc);
    acc = fma2(gp[9],  v4.y, acc);
    acc = fma2(gp[10], v5.x, acc);
    return acc;
}

__global__ void __launch_bounds__(256) quantize_kernel(
    const float* __restrict__ imu,
    const float* __restrict__ codebook,
    float* __restrict__ out) {

    __shared__ __align__(16) float sp[NPAIRS * PROW];   // 24 KB
    int tid = threadIdx.x;
    for (int i = tid; i < NPAIRS * PROW; i += 256) sp[i] = g_p32[i];
    __syncthreads();

    int row = blockIdx.x * 256 + tid;     // grid covers exactly NROWS
    int b = row >> 12;
    int t = row & 4095;

    // mean phase over channels (sequential, deterministic)
    const float* phbase = g_phase_scratch + (size_t)(b * C_DIM) * T_DIM + t;
    float ph = 0.0f;
    #pragma unroll
    for (int c = 0; c < 9; c++) ph += phbase[(size_t)c * T_DIM];
    ph *= (1.0f / 9.0f);

    // 11-dim raw feature, packed into both f32x2 lanes
    float g[11];
    const float* ib = imu + (size_t)(b * C_DIM) * T_DIM + t;
    #pragma unroll
    for (int c = 0; c < 9; c++) g[c] = ib[(size_t)c * T_DIM];
    g[9]  = cosf(ph);
    g[10] = sinf(ph);

    unsigned long long gp[11];
    #pragma unroll
    for (int i = 0; i < 11; i++) gp[i] = pack2(g[i], g[i]);

    float best  = -FLT_MAX;
    float best2 = -FLT_MAX;
    int   bidx  = 0;

    #pragma unroll 2
    for (int j = 0; j < NPAIRS; j++) {
        float s0, s1;
        unpack2(score_pair(sp, j, gp), s0, s1);
        if (s0 > best)       { best2 = best; best = s0; bidx = 2 * j; }
        else if (s0 > best2) { best2 = s0; }
        if (s1 > best)       { best2 = best; best = s1; bidx = 2 * j + 1; }
        else if (s1 > best2) { best2 = s1; }
    }

    // Near-tie: collect candidates within window, fp64-rerank ONLY those.
    if (best - best2 < 1e-3f) {
        int cand[8];
        int nc = 0;
        float thr = best - 2e-3f;
        #pragma unroll 2
        for (int j = 0; j < NPAIRS; j++) {
            float s0, s1;
            unpack2(score_pair(sp, j, gp), s0, s1);
            if (s0 >= thr && nc < 8) cand[nc++] = 2 * j;
            if (s1 >= thr && nc < 8) cand[nc++] = 2 * j + 1;
        }
        double gd[11];
        #pragma unroll
        for (int i = 0; i < 11; i++) gd[i] = (double)g[i];
        double bd = -1.0e300;
        int bi = bidx;
        for (int m = 0; m < nc; m++) {
            int j = cand[m];
            const double* pr = g_p64 + j * PDIM;
            double s0 = pr[11];
            double s1 = 0.0;
            #pragma unroll
            for (int i = 0; i < 10; i += 2) {
                s0 += gd[i]     * pr[i];
                s1 += gd[i + 1] * pr[i + 1];
            }
            s0 += gd[10] * pr[10];
            double s = s0 + s1;
            if (s > bd) { bd = s; bi = j; }   // cand ascending -> lowest idx wins ties
        }
        bidx = bi;
    }

    // outputs: quantized (gather), index, phase
    const float4* cb = (const float4*)(codebook + (size_t)bidx * CODE_DIM);
    float4* oq = (float4*)(out + (size_t)row * CODE_DIM);
    #pragma unroll
    for (int i = 0; i < CODE_DIM / 4; i++) oq[i] = cb[i];
    out[IDX_OFF + row] = (float)bidx;
    out[PH_OFF + row] = ph;
}

// ---------------------------------------------------------------------------
extern "C" void kernel_launch(void* const* d_in, const int* in_sizes, int n_in,
                              void* d_out, int out_size) {
    const float* imu      = (const float*)d_in[0];
    const float* W_mag    = (const float*)d_in[1];
    const float* b_mag    = (const float*)d_in[2];
    const float* W_phase  = (const float*)d_in[3];
    const float* b_phase  = (const float*)d_in[4];
    const float* codebook = (const float*)d_in[5];
    float* out = (float*)d_out;

    // 40KB dynamic smem: 4096 buf + 1024 twiddle float2
    phase_kernel<<<B_DIM * C_DIM, 512, 5120 * sizeof(float2)>>>(imu);
    precompute_kernel<<<NCODES, 32>>>(W_mag, b_mag, W_phase, b_phase, codebook);
    quantize_kernel<<<NROWS / 256, 256>>>(imu, codebook, out);
}

// round 5
// speedup vs baseline: 3.5148x; 1.0665x over previous
#include <cuda_runtime.h>
#include <math.h>
#include <float.h>

// Problem constants
#define B_DIM 32
#define C_DIM 9
#define T_DIM 4096
#define NROWS (B_DIM * T_DIM)          // 131072
#define NHALF (NROWS / 2)              // 65536
#define NCODES 512
#define CODE_DIM 64
#define HALF_DIM 32
#define PDIM 12                        // 11 feature dims + bias
#define DROW (PDIM * 2)                // 24 floats per code (lane-duplicated)

#define IDX_OFF (NROWS * CODE_DIM)     // 8388608
#define PH_OFF (IDX_OFF + NROWS)       // 8519680

// Scratch (no cudaMalloc allowed)
__device__ float  g_phase_scratch[B_DIM * C_DIM * T_DIM];
__device__ float  g_p32d[NCODES * DROW];    // lane-duplicated fp32 table
__device__ double g_p64[NCODES * PDIM];
__device__ int    g_fix_count;
__device__ int    g_fix_list[NROWS];

// ---------------------------------------------------------------------------
// FFT helpers (radix-4, 4096 = 4^6)
// ---------------------------------------------------------------------------
__device__ __forceinline__ float2 cmul(float2 a, float2 b) {
    return make_float2(fmaf(a.x, b.x, -a.y * b.y), fmaf(a.x, b.y, a.y * b.x));
}

// DIT: digit-reversed input -> natural output. tw[k] = exp(-2*pi*i*k/4096)
__device__ void fft4096_r4_dit(float2* __restrict__ buf,
                               const float2* __restrict__ tw, int tid) {
    #pragma unroll 1
    for (int s = 0; s < 6; s++) {
        int quarter = 1 << (2 * s);
        int rstep   = 1024 >> (2 * s);
        #pragma unroll
        for (int q = tid; q < 1024; q += 512) {
            int j   = q & (quarter - 1);
            int grp = q >> (2 * s);
            int pos = grp * (quarter << 2) + j;

            float2 w1 = tw[j * rstep];
            float2 w2 = cmul(w1, w1);
            float2 w3 = cmul(w2, w1);

            float2 a0 = buf[pos];
            float2 a1 = cmul(buf[pos + quarter],     w1);
            float2 a2 = cmul(buf[pos + 2 * quarter], w2);
            float2 a3 = cmul(buf[pos + 3 * quarter], w3);

            float2 t0 = make_float2(a0.x + a2.x, a0.y + a2.y);
            float2 t1 = make_float2(a0.x - a2.x, a0.y - a2.y);
            float2 t2 = make_float2(a1.x + a3.x, a1.y + a3.y);
            float2 t3 = make_float2(a1.x - a3.x, a1.y - a3.y);

            buf[pos]               = make_float2(t0.x + t2.x, t0.y + t2.y);
            buf[pos + quarter]     = make_float2(t1.x + t3.y, t1.y - t3.x);
            buf[pos + 2 * quarter] = make_float2(t0.x - t2.x, t0.y - t2.y);
            buf[pos + 3 * quarter] = make_float2(t1.x - t3.y, t1.y + t3.x);
        }
        __syncthreads();
    }
}

// DIF: natural input -> digit-reversed output. Same DFT sign convention.
__device__ void fft4096_r4_dif(float2* __restrict__ buf,
                               const float2* __restrict__ tw, int tid) {
    #pragma unroll 1
    for (int s = 0; s < 6; s++) {
        int quarter = 1024 >> (2 * s);
        int tstep   = 1 << (2 * s);
        int shift   = 10 - 2 * s;
        #pragma unroll
        for (int q = tid; q < 1024; q += 512) {
            int j   = q & (quarter - 1);
            int grp = q >> shift;
            int pos = grp * (quarter << 2) + j;

            float2 a0 = buf[pos];
            float2 a1 = buf[pos + quarter];
            float2 a2 = buf[pos + 2 * quarter];
            float2 a3 = buf[pos + 3 * quarter];

            float2 t0 = make_float2(a0.x + a2.x, a0.y + a2.y);
            float2 t1 = make_float2(a0.x - a2.x, a0.y - a2.y);
            float2 t2 = make_float2(a1.x + a3.x, a1.y + a3.y);
            float2 t3 = make_float2(a1.x - a3.x, a1.y - a3.y);

            float2 b0 = make_float2(t0.x + t2.x, t0.y + t2.y);
            float2 b1 = make_float2(t1.x + t3.y, t1.y - t3.x);  // t1 - i*t3
            float2 b2 = make_float2(t0.x - t2.x, t0.y - t2.y);
            float2 b3 = make_float2(t1.x - t3.y, t1.y + t3.x);  // t1 + i*t3

            float2 w1 = tw[j * tstep];
            float2 w2 = cmul(w1, w1);
            float2 w3 = cmul(w2, w1);

            buf[pos]               = b0;
            buf[pos + quarter]     = cmul(b1, w1);
            buf[pos + 2 * quarter] = cmul(b2, w2);
            buf[pos + 3 * quarter] = cmul(b3, w3);
        }
        __syncthreads();
    }
}

// ---------------------------------------------------------------------------
// Kernel 1: analytic-signal phase. DIF forward (natural->digit-rev), Hilbert
// multiplier applied in digit-reversed space, DIT back (digit-rev->natural).
// One block per (b, c), 512 threads.
// ---------------------------------------------------------------------------
__global__ void phase_kernel(const float* __restrict__ imu) {
    extern __shared__ float2 sm[];
    float2* buf = sm;          // 4096
    float2* tw  = sm + 4096;   // 1024

    int tid = threadIdx.x;
    int bc  = blockIdx.x;      // 0..287

    for (int k = tid; k < 1024; k += 512) {
        float sv, cv;
        sincospif(-(float)k * (1.0f / 2048.0f), &sv, &cv);
        tw[k] = make_float2(cv, sv);
    }

    const float* x = imu + (size_t)bc * T_DIM;
    for (int i = tid; i < 4096; i += 512) {
        buf[i] = make_float2(x[i], 0.0f);   // natural order, coalesced
    }
    __syncthreads();

    // Forward FFT (output digit-reversed: position p holds X[digrev4(p)])
    fft4096_r4_dif(buf, tw, tid);

    // Hilbert multiplier + conjugate, in digit-reversed index space.
    // k = digrev4(p):  k==0 <=> p==0;  k==2048 <=> p==2;  k>=2048 <=> (p&3)>=2
    for (int p = tid; p < 4096; p += 512) {
        int pm = p & 3;
        float hm = (pm >= 2) ? 0.0f : 2.0f;
        if (p == 0 || p == 2) hm = 1.0f;
        float2 v = buf[p];
        buf[p] = make_float2(v.x * hm, -v.y * hm);
    }
    __syncthreads();

    // Inverse via conj trick: DIT consumes digit-reversed input directly.
    fft4096_r4_dit(buf, tw, tid);

    float* dst = g_phase_scratch + (size_t)bc * T_DIM;
    for (int i = tid; i < 4096; i += 512) {
        float2 z = buf[i];
        dst[i] = atan2f(-z.y, z.x);
    }
}

// ---------------------------------------------------------------------------
// Kernel 2: precompute per-code projected 12-dim tables (fp64 + dup fp32)
// score s_k = g . p_k[0:11] + p_k[11],  g=[imu0..8, cos(ph), sin(ph)]
// argmin d2 == argmax s
// ---------------------------------------------------------------------------
__device__ __forceinline__ double warp_sum_d(double v) {
    #pragma unroll
    for (int m = 16; m > 0; m >>= 1) v += __shfl_xor_sync(0xFFFFFFFFu, v, m);
    return v;
}

__global__ void precompute_kernel(const float* __restrict__ W_mag,
                                  const float* __restrict__ b_mag,
                                  const float* __restrict__ W_phase,
                                  const float* __restrict__ b_phase,
                                  const float* __restrict__ codebook) {
    int k = blockIdx.x;
    int d = threadIdx.x;     // 0..31
    const float* c = codebook + k * CODE_DIM;

    if (k == 0 && d == 0) g_fix_count = 0;   // reset fixup list every replay

    double cm = (double)c[d];
    double cp = (double)c[HALF_DIM + d];

    double u[9], v[9];
    #pragma unroll
    for (int i = 0; i < 9; i++) {
        u[i] = (double)W_mag[d * 9 + i] * cm;
        v[i] = (double)W_phase[d * 9 + i] * cp;
    }
    double w = (double)b_mag[d] * cm + (double)b_phase[d] * cp
             - 0.5 * (cm * cm + cp * cp);

    double p[PDIM];
    #pragma unroll
    for (int i = 0; i < 7; i++) p[i] = warp_sum_d(u[i] + v[i]);
    p[7]  = warp_sum_d(u[7]);
    p[8]  = warp_sum_d(u[8]);
    p[9]  = warp_sum_d(v[7]);
    p[10] = warp_sum_d(v[8]);
    p[11] = warp_sum_d(w);

    if (d == 0) {
        #pragma unroll
        for (int i = 0; i < PDIM; i++) {
            g_p64[k * PDIM + i] = p[i];
            float f = (float)p[i];
            g_p32d[k * DROW + i * 2]     = f;   // lane-duplicated
            g_p32d[k * DROW + i * 2 + 1] = f;
        }
    }
}

// ---------------------------------------------------------------------------
// Kernel 3: argmax over codes, two ROWS packed in the f32x2 lanes.
// One thread handles rows (r, r+NHALF). 256 threads/block, 256 blocks.
// ---------------------------------------------------------------------------
__device__ __forceinline__ unsigned long long pack2(float lo, float hi) {
    unsigned long long r;
    asm("mov.b64 %0, {%1, %2};" : "=l"(r) : "f"(lo), "f"(hi));
    return r;
}
__device__ __forceinline__ void unpack2(unsigned long long v, float& lo, float& hi) {
    asm("mov.b64 {%0, %1}, %2;" : "=f"(lo), "=f"(hi) : "l"(v));
}
__device__ __forceinline__ unsigned long long fma2(unsigned long long a,
                                                   unsigned long long b,
                                                   unsigned long long c) {
    unsigned long long d;
    asm("fma.rn.f32x2 %0, %1, %2, %3;" : "=l"(d) : "l"(a), "l"(b), "l"(c));
    return d;
}

__device__ __forceinline__ void load_features(const float* __restrict__ imu,
                                              int row, float* g, float& ph) {
    int b = row >> 12;
    int t = row & 4095;
    const float* phbase = g_phase_scratch + (size_t)(b * C_DIM) * T_DIM + t;
    float s = 0.0f;
    #pragma unroll
    for (int c = 0; c < 9; c++) s += phbase[(size_t)c * T_DIM];
    ph = s * (1.0f / 9.0f);
    const float* ib = imu + (size_t)(b * C_DIM) * T_DIM + t;
    #pragma unroll
    for (int c = 0; c < 9; c++) g[c] = ib[(size_t)c * T_DIM];
    g[9]  = cosf(ph);
    g[10] = sinf(ph);
}

__global__ void __launch_bounds__(256) quantize_kernel(
    const float* __restrict__ imu,
    const float* __restrict__ codebook,
    float* __restrict__ out) {

    __shared__ __align__(16) float sp[NCODES * DROW];   // 48 KB
    int tid = threadIdx.x;
    for (int i = tid; i < NCODES * DROW; i += 256) sp[i] = g_p32d[i];
    __syncthreads();

    int r0 = blockIdx.x * 256 + tid;
    int r1 = r0 + NHALF;

    float g0[11], g1[11], ph0, ph1;
    load_features(imu, r0, g0, ph0);
    load_features(imu, r1, g1, ph1);

    unsigned long long gp[11];
    #pragma unroll
    for (int i = 0; i < 11; i++) gp[i] = pack2(g0[i], g1[i]);

    float best0  = -FLT_MAX, best20 = -FLT_MAX;
    float best1  = -FLT_MAX, best21 = -FLT_MAX;
    int   bidx0 = 0, bidx1 = 0;

    #pragma unroll 4
    for (int j = 0; j < NCODES; j++) {
        const ulonglong2* pr = (const ulonglong2*)(sp + j * DROW);
        ulonglong2 v0 = pr[0];   // dims 0,1
        ulonglong2 v1 = pr[1];   // dims 2,3
        ulonglong2 v2 = pr[2];   // dims 4,5
        ulonglong2 v3 = pr[3];   // dims 6,7
        ulonglong2 v4 = pr[4];   // dims 8,9
        ulonglong2 v5 = pr[5];   // dims 10,11(bias)
        unsigned long long acc = v5.y;
        acc = fma2(gp[0],  v0.x, acc);
        acc = fma2(gp[1],  v0.y, acc);
        acc = fma2(gp[2],  v1.x, acc);
        acc = fma2(gp[3],  v1.y, acc);
        acc = fma2(gp[4],  v2.x, acc);
        acc = fma2(gp[5],  v2.y, acc);
        acc = fma2(gp[6],  v3.x, acc);
        acc = fma2(gp[7],  v3.y, acc);
        acc = fma2(gp[8],  v4.x, acc);
        acc = fma2(gp[9],  v4.y, acc);
        acc = fma2(gp[10], v5.x, acc);
        float s0, s1;
        unpack2(acc, s0, s1);
        // 2nd-max invariant: best2' = max(best2, min(s, best))
        best20 = fmaxf(best20, fminf(s0, best0));
        best21 = fmaxf(best21, fminf(s1, best1));
        bool c0 = s0 > best0;         // strict > keeps lowest index
        bool c1 = s1 > best1;
        best0 = c0 ? s0 : best0;
        best1 = c1 ? s1 : best1;
        bidx0 = c0 ? j : bidx0;
        bidx1 = c1 ? j : bidx1;
    }

    // Rare near-ties: defer to exact fp64 fixup kernel
    if (best0 - best20 < 1e-3f) {
        int slot = atomicAdd(&g_fix_count, 1);
        g_fix_list[slot] = r0;
    }
    if (best1 - best21 < 1e-3f) {
        int slot = atomicAdd(&g_fix_count, 1);
        g_fix_list[slot] = r1;
    }

    // outputs
    const float4* cb0 = (const float4*)(codebook + (size_t)bidx0 * CODE_DIM);
    const float4* cb1 = (const float4*)(codebook + (size_t)bidx1 * CODE_DIM);
    float4* oq0 = (float4*)(out + (size_t)r0 * CODE_DIM);
    float4* oq1 = (float4*)(out + (size_t)r1 * CODE_DIM);
    #pragma unroll
    for (int i = 0; i < CODE_DIM / 4; i++) oq0[i] = cb0[i];
    #pragma unroll
    for (int i = 0; i < CODE_DIM / 4; i++) oq1[i] = cb1[i];
    out[IDX_OFF + r0] = (float)bidx0;
    out[IDX_OFF + r1] = (float)bidx1;
    out[PH_OFF + r0] = ph0;
    out[PH_OFF + r1] = ph1;
}

// ---------------------------------------------------------------------------
// Kernel 4: exact fp64 rerank for flagged rows. One WARP per row:
// 32 lanes x 16 codes each, then shuffle argmax (ties -> lowest index).
// ---------------------------------------------------------------------------
__global__ void fixup_kernel(const float* __restrict__ imu,
                             const float* __restrict__ codebook,
                             float* __restrict__ out) {
    int n = g_fix_count;
    int lane = threadIdx.x & 31;
    int warp = (blockIdx.x * blockDim.x + threadIdx.x) >> 5;
    int nwarps = (gridDim.x * blockDim.x) >> 5;

    for (int i = warp; i < n; i += nwarps) {
        int row = g_fix_list[i];
        float gf[11], ph;
        load_features(imu, row, gf, ph);
        double gd[11];
        #pragma unroll
        for (int k = 0; k < 11; k++) gd[k] = (double)gf[k];

        double bd = -1.0e300;
        int bi = NCODES;
        for (int c = 0; c < 16; c++) {
            int j = lane * 16 + c;
            const double* pr = g_p64 + j * PDIM;
            double s0 = pr[11];
            double s1 = 0.0;
            #pragma unroll
            for (int k = 0; k < 10; k += 2) {
                s0 += gd[k]     * pr[k];
                s1 += gd[k + 1] * pr[k + 1];
            }
            s0 += gd[10] * pr[10];
            double s = s0 + s1;
            if (s > bd) { bd = s; bi = j; }
        }
        // warp argmax with lowest-index tie-break
        #pragma unroll
        for (int m = 16; m > 0; m >>= 1) {
            double od = __shfl_xor_sync(0xFFFFFFFFu, bd, m);
            int    oi = __shfl_xor_sync(0xFFFFFFFFu, bi, m);
            if (od > bd || (od == bd && oi < bi)) { bd = od; bi = oi; }
        }
        if (lane == 0) out[IDX_OFF + row] = (float)bi;
        // rewrite quantized row (lanes 0..15 write 4 floats each)
        if (lane < 16) {
            const float4* cb = (const float4*)(codebook + (size_t)bi * CODE_DIM);
            float4* oq = (float4*)(out + (size_t)row * CODE_DIM);
            oq[lane] = cb[lane];
        }
    }
}

// ---------------------------------------------------------------------------
extern "C" void kernel_launch(void* const* d_in, const int* in_sizes, int n_in,
                              void* d_out, int out_size) {
    const float* imu      = (const float*)d_in[0];
    const float* W_mag    = (const float*)d_in[1];
    const float* b_mag    = (const float*)d_in[2];
    const float* W_phase  = (const float*)d_in[3];
    const float* b_phase  = (const float*)d_in[4];
    const float* codebook = (const float*)d_in[5];
    float* out = (float*)d_out;

    phase_kernel<<<B_DIM * C_DIM, 512, 5120 * sizeof(float2)>>>(imu);
    precompute_kernel<<<NCODES, 32>>>(W_mag, b_mag, W_phase, b_phase, codebook);
    quantize_kernel<<<NHALF / 256, 256>>>(imu, codebook, out);
    fixup_kernel<<<148, 128>>>(imu, codebook, out);
}

// round 7
// speedup vs baseline: 3.7047x; 1.0540x over previous
#include <cuda_runtime.h>
#include <math.h>
#include <float.h>

// Problem constants
#define B_DIM 32
#define C_DIM 9
#define T_DIM 4096
#define NROWS (B_DIM * T_DIM)          // 131072
#define NQUAD (NROWS / 4)              // 32768
#define NCODES 512
#define CODE_DIM 64
#define HALF_DIM 32
#define PDIM 12                        // 11 feature dims + bias
#define DROW (PDIM * 2)                // 24 floats per code (lane-duplicated)
#define SCORE_SHIFT 32.0f              // uniform shift to center scores near 0

#define IDX_OFF (NROWS * CODE_DIM)     // 8388608
#define PH_OFF (IDX_OFF + NROWS)       // 8519680

// Scratch (no cudaMalloc allowed)
__device__ float  g_phase_scratch[B_DIM * C_DIM * T_DIM];
__device__ float  g_p32d[NCODES * DROW];    // lane-duplicated fp32 (shifted bias)
__device__ float  g_p32s[NCODES * PDIM];    // compact fp32 (shifted bias)
__device__ double g_p64[NCODES * PDIM];     // exact (unshifted)
__device__ int    g_fix_count;
__device__ int    g_fix_list[NROWS];

// ---------------------------------------------------------------------------
// FFT helpers (radix-4, 4096 = 4^6)
// ---------------------------------------------------------------------------
__device__ __forceinline__ float2 cmul(float2 a, float2 b) {
    return make_float2(fmaf(a.x, b.x, -a.y * b.y), fmaf(a.x, b.y, a.y * b.x));
}

// DIT: digit-reversed input -> natural output. tw[k] = exp(-2*pi*i*k/4096)
__device__ void fft4096_r4_dit(float2* __restrict__ buf,
                               const float2* __restrict__ tw, int tid) {
    #pragma unroll 1
    for (int s = 0; s < 6; s++) {
        int quarter = 1 << (2 * s);
        int rstep   = 1024 >> (2 * s);
        #pragma unroll
        for (int q = tid; q < 1024; q += 512) {
            int j   = q & (quarter - 1);
            int grp = q >> (2 * s);
            int pos = grp * (quarter << 2) + j;

            float2 w1 = tw[j * rstep];
            float2 w2 = cmul(w1, w1);
            float2 w3 = cmul(w2, w1);

            float2 a0 = buf[pos];
            float2 a1 = cmul(buf[pos + quarter],     w1);
            float2 a2 = cmul(buf[pos + 2 * quarter], w2);
            float2 a3 = cmul(buf[pos + 3 * quarter], w3);

            float2 t0 = make_float2(a0.x + a2.x, a0.y + a2.y);
            float2 t1 = make_float2(a0.x - a2.x, a0.y - a2.y);
            float2 t2 = make_float2(a1.x + a3.x, a1.y + a3.y);
            float2 t3 = make_float2(a1.x - a3.x, a1.y - a3.y);

            buf[pos]               = make_float2(t0.x + t2.x, t0.y + t2.y);
            buf[pos + quarter]     = make_float2(t1.x + t3.y, t1.y - t3.x);
            buf[pos + 2 * quarter] = make_float2(t0.x - t2.x, t0.y - t2.y);
            buf[pos + 3 * quarter] = make_float2(t1.x - t3.y, t1.y + t3.x);
        }
        __syncthreads();
    }
}

// DIF: natural input -> digit-reversed output.
__device__ void fft4096_r4_dif(float2* __restrict__ buf,
                               const float2* __restrict__ tw, int tid) {
    #pragma unroll 1
    for (int s = 0; s < 6; s++) {
        int quarter = 1024 >> (2 * s);
        int tstep   = 1 << (2 * s);
        int shift   = 10 - 2 * s;
        #pragma unroll
        for (int q = tid; q < 1024; q += 512) {
            int j   = q & (quarter - 1);
            int grp = q >> shift;
            int pos = grp * (quarter << 2) + j;

            float2 a0 = buf[pos];
            float2 a1 = buf[pos + quarter];
            float2 a2 = buf[pos + 2 * quarter];
            float2 a3 = buf[pos + 3 * quarter];

            float2 t0 = make_float2(a0.x + a2.x, a0.y + a2.y);
            float2 t1 = make_float2(a0.x - a2.x, a0.y - a2.y);
            float2 t2 = make_float2(a1.x + a3.x, a1.y + a3.y);
            float2 t3 = make_float2(a1.x - a3.x, a1.y - a3.y);

            float2 b0 = make_float2(t0.x + t2.x, t0.y + t2.y);
            float2 b1 = make_float2(t1.x + t3.y, t1.y - t3.x);
            float2 b2 = make_float2(t0.x - t2.x, t0.y - t2.y);
            float2 b3 = make_float2(t1.x - t3.y, t1.y + t3.x);

            float2 w1 = tw[j * tstep];
            float2 w2 = cmul(w1, w1);
            float2 w3 = cmul(w2, w1);

            buf[pos]               = b0;
            buf[pos + quarter]     = cmul(b1, w1);
            buf[pos + 2 * quarter] = cmul(b2, w2);
            buf[pos + 3 * quarter] = cmul(b3, w3);
        }
        __syncthreads();
    }
}

// ---------------------------------------------------------------------------
// Kernel 1: analytic-signal phase. DIF fwd, Hilbert in digit-rev space, DIT bk.
// ---------------------------------------------------------------------------
__global__ void phase_kernel(const float* __restrict__ imu) {
    extern __shared__ float2 sm[];
    float2* buf = sm;          // 4096
    float2* tw  = sm + 4096;   // 1024

    int tid = threadIdx.x;
    int bc  = blockIdx.x;      // 0..287

    for (int k = tid; k < 1024; k += 512) {
        float sv, cv;
        sincospif(-(float)k * (1.0f / 2048.0f), &sv, &cv);
        tw[k] = make_float2(cv, sv);
    }

    const float* x = imu + (size_t)bc * T_DIM;
    for (int i = tid; i < 4096; i += 512) {
        buf[i] = make_float2(x[i], 0.0f);
    }
    __syncthreads();

    fft4096_r4_dif(buf, tw, tid);

    // k = digrev4(p): k==0 <=> p==0; k==2048 <=> p==2; k>=2048 <=> (p&3)>=2
    for (int p = tid; p < 4096; p += 512) {
        int pm = p & 3;
        float hm = (pm >= 2) ? 0.0f : 2.0f;
        if (p == 0 || p == 2) hm = 1.0f;
        float2 v = buf[p];
        buf[p] = make_float2(v.x * hm, -v.y * hm);
    }
    __syncthreads();

    fft4096_r4_dit(buf, tw, tid);

    float* dst = g_phase_scratch + (size_t)bc * T_DIM;
    for (int i = tid; i < 4096; i += 512) {
        float2 z = buf[i];
        dst[i] = atan2f(-z.y, z.x);
    }
}

// ---------------------------------------------------------------------------
// Kernel 2: precompute per-code projected 12-dim tables
// ---------------------------------------------------------------------------
__device__ __forceinline__ double warp_sum_d(double v) {
    #pragma unroll
    for (int m = 16; m > 0; m >>= 1) v += __shfl_xor_sync(0xFFFFFFFFu, v, m);
    return v;
}

__global__ void precompute_kernel(const float* __restrict__ W_mag,
                                  const float* __restrict__ b_mag,
                                  const float* __restrict__ W_phase,
                                  const float* __restrict__ b_phase,
                                  const float* __restrict__ codebook) {
    int k = blockIdx.x;
    int d = threadIdx.x;     // 0..31
    const float* c = codebook + k * CODE_DIM;

    if (k == 0 && d == 0) g_fix_count = 0;

    double cm = (double)c[d];
    double cp = (double)c[HALF_DIM + d];

    double u[9], v[9];
    #pragma unroll
    for (int i = 0; i < 9; i++) {
        u[i] = (double)W_mag[d * 9 + i] * cm;
        v[i] = (double)W_phase[d * 9 + i] * cp;
    }
    double w = (double)b_mag[d] * cm + (double)b_phase[d] * cp
             - 0.5 * (cm * cm + cp * cp);

    double p[PDIM];
    #pragma unroll
    for (int i = 0; i < 7; i++) p[i] = warp_sum_d(u[i] + v[i]);
    p[7]  = warp_sum_d(u[7]);
    p[8]  = warp_sum_d(u[8]);
    p[9]  = warp_sum_d(v[7]);
    p[10] = warp_sum_d(v[8]);
    p[11] = warp_sum_d(w);

    if (d == 0) {
        #pragma unroll
        for (int i = 0; i < PDIM; i++) {
            g_p64[k * PDIM + i] = p[i];
            float f = (float)p[i];
            if (i == 11) f = (float)(p[i] + (double)SCORE_SHIFT);
            g_p32s[k * PDIM + i] = f;
            g_p32d[k * DROW + i * 2]     = f;
            g_p32d[k * DROW + i * 2 + 1] = f;
        }
    }
}

// ---------------------------------------------------------------------------
// Kernel 3: argmax over codes; 4 rows per thread (2 f32x2 accumulators),
// codes split across even/odd lane pairs. Index embedded in low 9 mantissa
// bits -> pure FMNMX tracking; near-ties deferred to exact fixup.
// ---------------------------------------------------------------------------
__device__ __forceinline__ unsigned long long pack2(float lo, float hi) {
    unsigned long long r;
    asm("mov.b64 %0, {%1, %2};" : "=l"(r) : "f"(lo), "f"(hi));
    return r;
}
__device__ __forceinline__ void unpack2(unsigned long long v, float& lo, float& hi) {
    asm("mov.b64 {%0, %1}, %2;" : "=f"(lo), "=f"(hi) : "l"(v));
}
__device__ __forceinline__ unsigned long long fma2(unsigned long long a,
                                                   unsigned long long b,
                                                   unsigned long long c) {
    unsigned long long d;
    asm("fma.rn.f32x2 %0, %1, %2, %3;" : "=l"(d) : "l"(a), "l"(b), "l"(c));
    return d;
}

__device__ __forceinline__ void load_features(const float* __restrict__ imu,
                                              int row, float* g, float& ph) {
    int b = row >> 12;
    int t = row & 4095;
    const float* phbase = g_phase_scratch + (size_t)(b * C_DIM) * T_DIM + t;
    float s = 0.0f;
    #pragma unroll
    for (int c = 0; c < 9; c++) s += phbase[(size_t)c * T_DIM];
    ph = s * (1.0f / 9.0f);
    const float* ib = imu + (size_t)(b * C_DIM) * T_DIM + t;
    #pragma unroll
    for (int c = 0; c < 9; c++) g[c] = ib[(size_t)c * T_DIM];
    g[9]  = cosf(ph);
    g[10] = sinf(ph);
}

__device__ __forceinline__ float embed_idx(float s, unsigned ikey) {
    return __uint_as_float((__float_as_uint(s) & 0xFFFFFE00u) | ikey);
}

__global__ void __launch_bounds__(256) quantize_kernel(
    const float* __restrict__ imu,
    const float* __restrict__ codebook,
    float* __restrict__ out) {

    __shared__ __align__(16) float sp[NCODES * DROW];   // 48 KB
    int tid = threadIdx.x;
    for (int i = tid; i < NCODES * DROW; i += 256) sp[i] = g_p32d[i];
    __syncthreads();

    int half = tid & 1;                        // code-range half
    int q = blockIdx.x * 128 + (tid >> 1);     // quad id, same for lane pair
    int rows[4];
    #pragma unroll
    for (int r = 0; r < 4; r++) rows[r] = q + r * NQUAD;

    float g0[11], g1[11], g2[11], g3[11], ph[4];
    load_features(imu, rows[0], g0, ph[0]);
    load_features(imu, rows[1], g1, ph[1]);
    load_features(imu, rows[2], g2, ph[2]);
    load_features(imu, rows[3], g3, ph[3]);

    unsigned long long gpA[11], gpB[11];
    #pragma unroll
    for (int i = 0; i < 11; i++) {
        gpA[i] = pack2(g0[i], g1[i]);
        gpB[i] = pack2(g2[i], g3[i]);
    }

    float best[4], best2[4];
    #pragma unroll
    for (int r = 0; r < 4; r++) { best[r] = -FLT_MAX; best2[r] = -FLT_MAX; }

    int jbase = half * 256;
    #pragma unroll 4
    for (int jj = 0; jj < 256; jj++) {
        int j = jbase + jj;
        const ulonglong2* pr = (const ulonglong2*)(sp + j * DROW);
        ulonglong2 v0 = pr[0];
        ulonglong2 v1 = pr[1];
        ulonglong2 v2 = pr[2];
        ulonglong2 v3 = pr[3];
        ulonglong2 v4 = pr[4];
        ulonglong2 v5 = pr[5];
        unsigned long long aA = v5.y, aB = v5.y;
        aA = fma2(gpA[0],  v0.x, aA);  aB = fma2(gpB[0],  v0.x, aB);
        aA = fma2(gpA[1],  v0.y, aA);  aB = fma2(gpB[1],  v0.y, aB);
        aA = fma2(gpA[2],  v1.x, aA);  aB = fma2(gpB[2],  v1.x, aB);
        aA = fma2(gpA[3],  v1.y, aA);  aB = fma2(gpB[3],  v1.y, aB);
        aA = fma2(gpA[4],  v2.x, aA);  aB = fma2(gpB[4],  v2.x, aB);
        aA = fma2(gpA[5],  v2.y, aA);  aB = fma2(gpB[5],  v2.y, aB);
        aA = fma2(gpA[6],  v3.x, aA);  aB = fma2(gpB[6],  v3.x, aB);
        aA = fma2(gpA[7],  v3.y, aA);  aB = fma2(gpB[7],  v3.y, aB);
        aA = fma2(gpA[8],  v4.x, aA);  aB = fma2(gpB[8],  v4.x, aB);
        aA = fma2(gpA[9],  v4.y, aA);  aB = fma2(gpB[9],  v4.y, aB);
        aA = fma2(gpA[10], v5.x, aA);  aB = fma2(gpB[10], v5.x, aB);
        float s[4];
        unpack2(aA, s[0], s[1]);
        unpack2(aB, s[2], s[3]);
        unsigned ikey = (unsigned)(511 - j);
        #pragma unroll
        for (int r = 0; r < 4; r++) {
            float e = embed_idx(s[r], ikey);
            float t = fminf(e, best[r]);
            best2[r] = fmaxf(best2[r], t);
            best[r]  = fmaxf(best[r], e);
        }
    }

    // merge across the lane pair (each lane covered half the codes)
    #pragma unroll
    for (int r = 0; r < 4; r++) {
        float ob  = __shfl_xor_sync(0xFFFFFFFFu, best[r], 1);
        float ob2 = __shfl_xor_sync(0xFFFFFFFFu, best2[r], 1);
        float nb  = fmaxf(best[r], ob);
        float nb2 = fmaxf(fminf(best[r], ob), fmaxf(best2[r], ob2));
        best[r] = nb;
        best2[r] = nb2;
    }

    #pragma unroll
    for (int r = 0; r < 4; r++) {
        int bidx = 511 - (int)(__float_as_uint(best[r]) & 511u);
        int row = rows[r];
        // both lanes have identical merged values; split the 64-float copy
        const float4* cb = (const float4*)(codebook + (size_t)bidx * CODE_DIM);
        float4* oq = (float4*)(out + (size_t)row * CODE_DIM);
        #pragma unroll
        for (int i = 0; i < 8; i++) oq[half * 8 + i] = cb[half * 8 + i];
        if (half == 0) {
            out[IDX_OFF + row] = (float)bidx;
            out[PH_OFF + row] = ph[r];
            if (best[r] - best2[r] < 6e-3f) {
                int slot = atomicAdd(&g_fix_count, 1);
                g_fix_list[slot] = row;
            }
        }
    }
}

// ---------------------------------------------------------------------------
// Kernel 4: exact rerank for flagged rows. One warp per row.
// Pass 1: fp32 scores (16 codes/lane). Pass 2: fp64 ONLY for candidates
// within 1e-3 of the warp max. Exact argmax, lowest index on ties.
// ---------------------------------------------------------------------------
__global__ void fixup_kernel(const float* __restrict__ imu,
                             const float* __restrict__ codebook,
                             float* __restrict__ out) {
    int n = g_fix_count;
    int lane = threadIdx.x & 31;
    int warp = (blockIdx.x * blockDim.x + threadIdx.x) >> 5;
    int nwarps = (gridDim.x * blockDim.x) >> 5;

    for (int i = warp; i < n; i += nwarps) {
        int row = g_fix_list[i];
        float gf[11], ph;
        load_features(imu, row, gf, ph);

        // pass 1: fp32 scores, remember per-lane values
        float sc[16];
        float lbest = -FLT_MAX;
        #pragma unroll
        for (int c = 0; c < 16; c++) {
            int j = c * 32 + lane;
            const float* pr = g_p32s + j * PDIM;
            float s = pr[11];
            #pragma unroll
            for (int k = 0; k < 11; k++) s = fmaf(gf[k], pr[k], s);
            sc[c] = s;
            lbest = fmaxf(lbest, s);
        }
        #pragma unroll
        for (int m = 16; m > 0; m >>= 1)
            lbest = fmaxf(lbest, __shfl_xor_sync(0xFFFFFFFFu, lbest, m));
        float thr = lbest - 1e-3f;

        // pass 2: fp64 for candidates only
        double gd[11];
        #pragma unroll
        for (int k = 0; k < 11; k++) gd[k] = (double)gf[k];
        double bd = -1.0e300;
        int bi = NCODES;
        #pragma unroll 1
        for (int c = 0; c < 16; c++) {
            if (sc[c] >= thr) {
                int j = c * 32 + lane;
                const double* pr = g_p64 + j * PDIM;
                double s0 = pr[11];
                double s1 = 0.0;
                #pragma unroll
                for (int k = 0; k < 10; k += 2) {
                    s0 += gd[k]     * pr[k];
                    s1 += gd[k + 1] * pr[k + 1];
                }
                s0 += gd[10] * pr[10];
                double s = s0 + s1;
                if (s > bd || (s == bd && j < bi)) { bd = s; bi = j; }
            }
        }
        #pragma unroll
        for (int m = 16; m > 0; m >>= 1) {
            double od = __shfl_xor_sync(0xFFFFFFFFu, bd, m);
            int    oi = __shfl_xor_sync(0xFFFFFFFFu, bi, m);
            if (od > bd || (od == bd && oi < bi)) { bd = od; bi = oi; }
        }
        if (lane == 0) out[IDX_OFF + row] = (float)bi;
        if (lane < 16) {
            const float4* cb = (const float4*)(codebook + (size_t)bi * CODE_DIM);
            float4* oq = (float4*)(out + (size_t)row * CODE_DIM);
            oq[lane] = cb[lane];
        }
    }
}

// ---------------------------------------------------------------------------
extern "C" void kernel_launch(void* const* d_in, const int* in_sizes, int n_in,
                              void* d_out, int out_size) {
    const float* imu      = (const float*)d_in[0];
    const float* W_mag    = (const float*)d_in[1];
    const float* b_mag    = (const float*)d_in[2];
    const float* W_phase  = (const float*)d_in[3];
    const float* b_phase  = (const float*)d_in[4];
    const float* codebook = (const float*)d_in[5];
    float* out = (float*)d_out;

    phase_kernel<<<B_DIM * C_DIM, 512, 5120 * sizeof(float2)>>>(imu);
    precompute_kernel<<<NCODES, 32>>>(W_mag, b_mag, W_phase, b_phase, codebook);
    quantize_kernel<<<256, 256>>>(imu, codebook, out);
    fixup_kernel<<<148, 256>>>(imu, codebook, out);
}

// round 10
// speedup vs baseline: 3.7706x; 1.0178x over previous
#include <cuda_runtime.h>
#include <math.h>
#include <float.h>

// Problem constants
#define B_DIM 32
#define C_DIM 9
#define T_DIM 4096
#define NROWS (B_DIM * T_DIM)          // 131072
#define NHALF (NROWS / 2)              // 65536
#define NCODES 512
#define CODE_DIM 64
#define HALF_DIM 32
#define PDIM 12                        // 11 feature dims + bias
#define PSTRIDE 13                     // padded stride for fixup smem table
#define DROW (PDIM * 2)                // 24 floats per code (lane-duplicated)
#define SCORE_SHIFT 32.0f
#define FIX_THR 2e-3f

#define IDX_OFF (NROWS * CODE_DIM)     // 8388608
#define PH_OFF (IDX_OFF + NROWS)       // 8519680

// Scratch (no cudaMalloc allowed)
__device__ float  g_phase_scratch[B_DIM * C_DIM * T_DIM];
__device__ float  g_p32d[NCODES * DROW];     // pair-interleaved, lane-duplicated
__device__ float  g_p32s[NCODES * PSTRIDE];  // compact padded fp32 (shifted bias)
__device__ double g_p64[NCODES * PDIM];      // exact (unshifted)
__device__ int    g_fix_count;
__device__ int    g_fix_list[NROWS];

// ---------------------------------------------------------------------------
// FFT helpers (radix-4, 4096 = 4^6)
// ---------------------------------------------------------------------------
__device__ __forceinline__ float2 cmul(float2 a, float2 b) {
    return make_float2(fmaf(a.x, b.x, -a.y * b.y), fmaf(a.x, b.y, a.y * b.x));
}

// DIT stages [sstart..5]: digit-reversed input -> natural output.
__device__ void fft4096_r4_dit(float2* __restrict__ buf,
                               const float2* __restrict__ tw, int tid, int sstart) {
    #pragma unroll 1
    for (int s = sstart; s < 6; s++) {
        int quarter = 1 << (2 * s);
        int rstep   = 1024 >> (2 * s);
        #pragma unroll
        for (int q = tid; q < 1024; q += 512) {
            int j   = q & (quarter - 1);
            int grp = q >> (2 * s);
            int pos = grp * (quarter << 2) + j;

            float2 w1 = tw[j * rstep];
            float2 w2 = cmul(w1, w1);
            float2 w3 = cmul(w2, w1);

            float2 a0 = buf[pos];
            float2 a1 = cmul(buf[pos + quarter],     w1);
            float2 a2 = cmul(buf[pos + 2 * quarter], w2);
            float2 a3 = cmul(buf[pos + 3 * quarter], w3);

            float2 t0 = make_float2(a0.x + a2.x, a0.y + a2.y);
            float2 t1 = make_float2(a0.x - a2.x, a0.y - a2.y);
            float2 t2 = make_float2(a1.x + a3.x, a1.y + a3.y);
            float2 t3 = make_float2(a1.x - a3.x, a1.y - a3.y);

            buf[pos]               = make_float2(t0.x + t2.x, t0.y + t2.y);
            buf[pos + quarter]     = make_float2(t1.x + t3.y, t1.y - t3.x);
            buf[pos + 2 * quarter] = make_float2(t0.x - t2.x, t0.y - t2.y);
            buf[pos + 3 * quarter] = make_float2(t1.x - t3.y, t1.y + t3.x);
        }
        __syncthreads();
    }
}

// DIF: natural input -> digit-reversed output.
__device__ void fft4096_r4_dif(float2* __restrict__ buf,
                               const float2* __restrict__ tw, int tid) {
    #pragma unroll 1
    for (int s = 0; s < 6; s++) {
        int quarter = 1024 >> (2 * s);
        int tstep   = 1 << (2 * s);
        int shift   = 10 - 2 * s;
        #pragma unroll
        for (int q = tid; q < 1024; q += 512) {
            int j   = q & (quarter - 1);
            int grp = q >> shift;
            int pos = grp * (quarter << 2) + j;

            float2 a0 = buf[pos];
            float2 a1 = buf[pos + quarter];
            float2 a2 = buf[pos + 2 * quarter];
            float2 a3 = buf[pos + 3 * quarter];

            float2 t0 = make_float2(a0.x + a2.x, a0.y + a2.y);
            float2 t1 = make_float2(a0.x - a2.x, a0.y - a2.y);
            float2 t2 = make_float2(a1.x + a3.x, a1.y + a3.y);
            float2 t3 = make_float2(a1.x - a3.x, a1.y - a3.y);

            float2 b0 = make_float2(t0.x + t2.x, t0.y + t2.y);
            float2 b1 = make_float2(t1.x + t3.y, t1.y - t3.x);
            float2 b2 = make_float2(t0.x - t2.x, t0.y - t2.y);
            float2 b3 = make_float2(t1.x - t3.y, t1.y + t3.x);

            float2 w1 = tw[j * tstep];
            float2 w2 = cmul(w1, w1);
            float2 w3 = cmul(w2, w1);

            buf[pos]               = b0;
            buf[pos + quarter]     = cmul(b1, w1);
            buf[pos + 2 * quarter] = cmul(b2, w2);
            buf[pos + 3 * quarter] = cmul(b3, w3);
        }
        __syncthreads();
    }
}

// ---------------------------------------------------------------------------
// Kernel 1: analytic-signal phase. DIF fwd; Hilbert*conj FUSED into DIT
// stage 0 (half the digit-reversed spectrum is zeroed -> butterflies collapse);
// DIT stages 1..5; atan2.
// ---------------------------------------------------------------------------
__global__ void phase_kernel(const float* __restrict__ imu) {
    extern __shared__ float2 sm[];
    float2* buf = sm;          // 4096
    float2* tw  = sm + 4096;   // 1024

    int tid = threadIdx.x;
    int bc  = blockIdx.x;      // 0..287

    for (int k = tid; k < 1024; k += 512) {
        float sv, cv;
        sincospif(-(float)k * (1.0f / 2048.0f), &sv, &cv);
        tw[k] = make_float2(cv, sv);
    }

    const float* x = imu + (size_t)bc * T_DIM;
    for (int i = tid; i < 4096; i += 512) {
        buf[i] = make_float2(x[i], 0.0f);
    }
    __syncthreads();

    fft4096_r4_dif(buf, tw, tid);

    // Fused: Hilbert multiplier + conjugate + DIT stage 0.
    // In digit-rev space position p: hm=2 for (p&3)<2, 0 otherwise;
    // overrides: p==0 -> 1, p==2 -> 1. So within group pos=4g:
    //   g>0:  a0=2conj(x0), a1=2conj(x1), a2=a3=0
    //   g==0: a0=conj(x0),  a1=2conj(x1), a2=conj(x2), a3=0
    for (int g = tid; g < 1024; g += 512) {
        int pos = g * 4;
        float2 x0 = buf[pos];
        float2 x1 = buf[pos + 1];
        float2 a1 = make_float2(2.0f * x1.x, -2.0f * x1.y);
        float2 t0, t1;
        if (g == 0) {
            float2 x2 = buf[2];
            float2 a0 = make_float2(x0.x, -x0.y);
            float2 a2 = make_float2(x2.x, -x2.y);
            t0 = make_float2(a0.x + a2.x, a0.y + a2.y);
            t1 = make_float2(a0.x - a2.x, a0.y - a2.y);
        } else {
            float2 a0 = make_float2(2.0f * x0.x, -2.0f * x0.y);
            t0 = a0;
            t1 = a0;
        }
        buf[pos]     = make_float2(t0.x + a1.x, t0.y + a1.y);
        buf[pos + 1] = make_float2(t1.x + a1.y, t1.y - a1.x);   // t1 - i*a1
        buf[pos + 2] = make_float2(t0.x - a1.x, t0.y - a1.y);
        buf[pos + 3] = make_float2(t1.x - a1.y, t1.y + a1.x);   // t1 + i*a1
    }
    __syncthreads();

    fft4096_r4_dit(buf, tw, tid, 1);

    float* dst = g_phase_scratch + (size_t)bc * T_DIM;
    for (int i = tid; i < 4096; i += 512) {
        float2 z = buf[i];
        dst[i] = atan2f(-z.y, z.x);
    }
}

// ---------------------------------------------------------------------------
// Kernel 2: precompute per-code projected 12-dim tables
// ---------------------------------------------------------------------------
__device__ __forceinline__ double warp_sum_d(double v) {
    #pragma unroll
    for (int m = 16; m > 0; m >>= 1) v += __shfl_xor_sync(0xFFFFFFFFu, v, m);
    return v;
}

__global__ void precompute_kernel(const float* __restrict__ W_mag,
                                  const float* __restrict__ b_mag,
                                  const float* __restrict__ W_phase,
                                  const float* __restrict__ b_phase,
                                  const float* __restrict__ codebook) {
    int k = blockIdx.x;
    int d = threadIdx.x;     // 0..31
    const float* c = codebook + k * CODE_DIM;

    if (k == 0 && d == 0) g_fix_count = 0;

    double cm = (double)c[d];
    double cp = (double)c[HALF_DIM + d];

    double u[9], v[9];
    #pragma unroll
    for (int i = 0; i < 9; i++) {
        u[i] = (double)W_mag[d * 9 + i] * cm;
        v[i] = (double)W_phase[d * 9 + i] * cp;
    }
    double w = (double)b_mag[d] * cm + (double)b_phase[d] * cp
             - 0.5 * (cm * cm + cp * cp);

    double p[PDIM];
    #pragma unroll
    for (int i = 0; i < 7; i++) p[i] = warp_sum_d(u[i] + v[i]);
    p[7]  = warp_sum_d(u[7]);
    p[8]  = warp_sum_d(u[8]);
    p[9]  = warp_sum_d(v[7]);
    p[10] = warp_sum_d(v[8]);
    p[11] = warp_sum_d(w);

    if (d == 0) {
        // pair-interleaved physical row: even lane codes [0,256) at 2*jj,
        // odd lane codes [256,512) at 2*jj+1 -> 96B address spacing, no conflicts
        int phys = (k & 255) * 2 + (k >> 8);
        #pragma unroll
        for (int i = 0; i < PDIM; i++) {
            g_p64[k * PDIM + i] = p[i];
            float f = (float)p[i];
            if (i == 11) f = (float)(p[i] + (double)SCORE_SHIFT);
            g_p32s[k * PSTRIDE + i] = f;
            g_p32d[phys * DROW + i * 2]     = f;
            g_p32d[phys * DROW + i * 2 + 1] = f;
        }
    }
}

// ---------------------------------------------------------------------------
// Kernel 3: argmax; 2 rows per thread packed in f32x2 lanes, codes split
// across even/odd lanes (256 each). 8-bit index embed, FMNMX tracking.
// 131072 threads -> 4096 warps (2x prior occupancy).
// ---------------------------------------------------------------------------
__device__ __forceinline__ unsigned long long pack2(float lo, float hi) {
    unsigned long long r;
    asm("mov.b64 %0, {%1, %2};" : "=l"(r) : "f"(lo), "f"(hi));
    return r;
}
__device__ __forceinline__ void unpack2(unsigned long long v, float& lo, float& hi) {
    asm("mov.b64 {%0, %1}, %2;" : "=f"(lo), "=f"(hi) : "l"(v));
}
__device__ __forceinline__ unsigned long long fma2(unsigned long long a,
                                                   unsigned long long b,
                                                   unsigned long long c) {
    unsigned long long d;
    asm("fma.rn.f32x2 %0, %1, %2, %3;" : "=l"(d) : "l"(a), "l"(b), "l"(c));
    return d;
}

__device__ __forceinline__ void load_features(const float* __restrict__ imu,
                                              int row, float* g, float& ph) {
    int b = row >> 12;
    int t = row & 4095;
    const float* phbase = g_phase_scratch + (size_t)(b * C_DIM) * T_DIM + t;
    float s = 0.0f;
    #pragma unroll
    for (int c = 0; c < 9; c++) s += phbase[(size_t)c * T_DIM];
    ph = s * (1.0f / 9.0f);
    const float* ib = imu + (size_t)(b * C_DIM) * T_DIM + t;
    #pragma unroll
    for (int c = 0; c < 9; c++) g[c] = ib[(size_t)c * T_DIM];
    g[9]  = cosf(ph);
    g[10] = sinf(ph);
}

__device__ __forceinline__ float embed8(float s, unsigned ikey) {
    return __uint_as_float((__float_as_uint(s) & 0xFFFFFF00u) | ikey);
}

__global__ void __launch_bounds__(256, 3) quantize_kernel(
    const float* __restrict__ imu,
    const float* __restrict__ codebook,
    float* __restrict__ out) {

    __shared__ __align__(16) float sp[NCODES * DROW];   // 48 KB
    int tid = threadIdx.x;
    for (int i = tid; i < NCODES * DROW; i += 256) sp[i] = g_p32d[i];
    __syncthreads();

    int half = tid & 1;                        // code-range half
    int q = blockIdx.x * 128 + (tid >> 1);     // pair id
    int r0 = q;
    int r1 = q + NHALF;

    float g0[11], g1[11], ph0, ph1;
    load_features(imu, r0, g0, ph0);
    load_features(imu, r1, g1, ph1);

    unsigned long long gp[11];
    #pragma unroll
    for (int i = 0; i < 11; i++) gp[i] = pack2(g0[i], g1[i]);

    float best0 = -FLT_MAX, best20 = -FLT_MAX;
    float best1 = -FLT_MAX, best21 = -FLT_MAX;

    #pragma unroll 4
    for (int jj = 0; jj < 256; jj++) {
        int phys = jj * 2 + half;
        const ulonglong2* pr = (const ulonglong2*)(sp + phys * DROW);
        ulonglong2 v0 = pr[0];
        ulonglong2 v1 = pr[1];
        ulonglong2 v2 = pr[2];
        ulonglong2 v3 = pr[3];
        ulonglong2 v4 = pr[4];
        ulonglong2 v5 = pr[5];
        unsigned long long acc = v5.y;
        acc = fma2(gp[0],  v0.x, acc);
        acc = fma2(gp[1],  v0.y, acc);
        acc = fma2(gp[2],  v1.x, acc);
        acc = fma2(gp[3],  v1.y, acc);
        acc = fma2(gp[4],  v2.x, acc);
        acc = fma2(gp[5],  v2.y, acc);
        acc = fma2(gp[6],  v3.x, acc);
        acc = fma2(gp[7],  v3.y, acc);
        acc = fma2(gp[8],  v4.x, acc);
        acc = fma2(gp[9],  v4.y, acc);
        acc = fma2(gp[10], v5.x, acc);
        float s0, s1;
        unpack2(acc, s0, s1);
        unsigned ikey = 255u - (unsigned)jj;
        float e0 = embed8(s0, ikey);
        float e1 = embed8(s1, ikey);
        best20 = fmaxf(best20, fminf(e0, best0));
        best0  = fmaxf(best0, e0);
        best21 = fmaxf(best21, fminf(e1, best1));
        best1  = fmaxf(best1, e1);
    }

    // merge across lane pair (ties -> even half = lower global index)
    int h0 = half, h1 = half;
    {
        float ob  = __shfl_xor_sync(0xFFFFFFFFu, best0, 1);
        float ob2 = __shfl_xor_sync(0xFFFFFFFFu, best20, 1);
        best20 = fmaxf(fmaxf(best20, ob2), fminf(best0, ob));
        bool take = (ob > best0) || (ob == best0 && half == 1);
        if (take) { best0 = ob; h0 = half ^ 1; }
    }
    {
        float ob  = __shfl_xor_sync(0xFFFFFFFFu, best1, 1);
        float ob2 = __shfl_xor_sync(0xFFFFFFFFu, best21, 1);
        best21 = fmaxf(fmaxf(best21, ob2), fminf(best1, ob));
        bool take = (ob > best1) || (ob == best1 && half == 1);
        if (take) { best1 = ob; h1 = half ^ 1; }
    }

    int bidx0 = h0 * 256 + (255 - (int)(__float_as_uint(best0) & 255u));
    int bidx1 = h1 * 256 + (255 - (int)(__float_as_uint(best1) & 255u));

    // outputs: gathers split across the lane pair
    const float4* cb0 = (const float4*)(codebook + (size_t)bidx0 * CODE_DIM);
    const float4* cb1 = (const float4*)(codebook + (size_t)bidx1 * CODE_DIM);
    float4* oq0 = (float4*)(out + (size_t)r0 * CODE_DIM);
    float4* oq1 = (float4*)(out + (size_t)r1 * CODE_DIM);
    #pragma unroll
    for (int i = 0; i < 8; i++) oq0[half * 8 + i] = cb0[half * 8 + i];
    #pragma unroll
    for (int i = 0; i < 8; i++) oq1[half * 8 + i] = cb1[half * 8 + i];

    if (half == 0) {
        out[IDX_OFF + r0] = (float)bidx0;
        out[IDX_OFF + r1] = (float)bidx1;
        out[PH_OFF + r0] = ph0;
        out[PH_OFF + r1] = ph1;
        if (best0 - best20 < FIX_THR) {
            int slot = atomicAdd(&g_fix_count, 1);
            g_fix_list[slot] = r0;
        }
        if (best1 - best21 < FIX_THR) {
            int slot = atomicAdd(&g_fix_count, 1);
            g_fix_list[slot] = r1;
        }
    }
}

// ---------------------------------------------------------------------------
// Kernel 4: exact rerank for flagged rows. Table staged in smem (stride 13 ->
// conflict-free). One warp per row; fp64 only for candidates near the max.
// ---------------------------------------------------------------------------
__global__ void __launch_bounds__(256) fixup_kernel(
    const float* __restrict__ imu,
    const float* __restrict__ codebook,
    float* __restrict__ out) {

    __shared__ float st[NCODES * PSTRIDE];   // 26 KB
    int tid = threadIdx.x;
    for (int i = tid; i < NCODES * PSTRIDE; i += 256) st[i] = g_p32s[i];
    __syncthreads();

    int n = g_fix_count;
    int lane = tid & 31;
    int warp = (blockIdx.x * blockDim.x + tid) >> 5;
    int nwarps = (gridDim.x * blockDim.x) >> 5;

    for (int i = warp; i < n; i += nwarps) {
        int row = g_fix_list[i];
        float gf[11], ph;
        load_features(imu, row, gf, ph);

        // pass 1: fp32 scores from smem
        float sc[16];
        float lbest = -FLT_MAX;
        #pragma unroll
        for (int c = 0; c < 16; c++) {
            const float* pr = st + (c * 32 + lane) * PSTRIDE;
            float s = pr[11];
            #pragma unroll
            for (int k = 0; k < 11; k++) s = fmaf(gf[k], pr[k], s);
            sc[c] = s;
            lbest = fmaxf(lbest, s);
        }
        #pragma unroll
        for (int m = 16; m > 0; m >>= 1)
            lbest = fmaxf(lbest, __shfl_xor_sync(0xFFFFFFFFu, lbest, m));
        float thr = lbest - 1e-3f;

        // pass 2: fp64 for candidates only
        double gd[11];
        #pragma unroll
        for (int k = 0; k < 11; k++) gd[k] = (double)gf[k];
        double bd = -1.0e300;
        int bi = NCODES;
        #pragma unroll 1
        for (int c = 0; c < 16; c++) {
            if (sc[c] >= thr) {
                int j = c * 32 + lane;
                const double* pr = g_p64 + j * PDIM;
                double s0 = pr[11];
                double s1 = 0.0;
                #pragma unroll
                for (int k = 0; k < 10; k += 2) {
                    s0 += gd[k]     * pr[k];
                    s1 += gd[k + 1] * pr[k + 1];
                }
                s0 += gd[10] * pr[10];
                double s = s0 + s1;
                if (s > bd || (s == bd && j < bi)) { bd = s; bi = j; }
            }
        }
        #pragma unroll
        for (int m = 16; m > 0; m >>= 1) {
            double od = __shfl_xor_sync(0xFFFFFFFFu, bd, m);
            int    oi = __shfl_xor_sync(0xFFFFFFFFu, bi, m);
            if (od > bd || (od == bd && oi < bi)) { bd = od; bi = oi; }
        }
        if (lane == 0) out[IDX_OFF + row] = (float)bi;
        if (lane < 16) {
            const float4* cb = (const float4*)(codebook + (size_t)bi * CODE_DIM);
            float4* oq = (float4*)(out + (size_t)row * CODE_DIM);
            oq[lane] = cb[lane];
        }
    }
}

// ---------------------------------------------------------------------------
extern "C" void kernel_launch(void* const* d_in, const int* in_sizes, int n_in,
                              void* d_out, int out_size) {
    const float* imu      = (const float*)d_in[0];
    const float* W_mag    = (const float*)d_in[1];
    const float* b_mag    = (const float*)d_in[2];
    const float* W_phase  = (const float*)d_in[3];
    const float* b_phase  = (const float*)d_in[4];
    const float* codebook = (const float*)d_in[5];
    float* out = (float*)d_out;

    phase_kernel<<<B_DIM * C_DIM, 512, 5120 * sizeof(float2)>>>(imu);
    precompute_kernel<<<NCODES, 32>>>(W_mag, b_mag, W_phase, b_phase, codebook);
    quantize_kernel<<<NROWS / 256, 256>>>(imu, codebook, out);
    fixup_kernel<<<296, 256>>>(imu, codebook, out);
}

// round 11
// speedup vs baseline: 4.3065x; 1.1421x over previous
#include <cuda_runtime.h>
#include <math.h>
#include <float.h>

// Problem constants
#define B_DIM 32
#define C_DIM 9
#define T_DIM 4096
#define NROWS (B_DIM * T_DIM)          // 131072
#define NHALF (NROWS / 2)              // 65536
#define NCODES 512
#define CODE_DIM 64
#define HALF_DIM 32
#define PDIM 12                        // 11 feature dims + bias
#define PSTRIDE 13                     // padded stride for fixup smem table
#define DROW (PDIM * 2)                // 24 floats per code (lane-duplicated)
#define SCORE_SHIFT 32.0f
#define FIX_THR 2e-3f

#define IDX_OFF (NROWS * CODE_DIM)     // 8388608
#define PH_OFF (IDX_OFF + NROWS)       // 8519680

// Scratch (no cudaMalloc allowed)
__device__ float  g_phase_scratch[B_DIM * C_DIM * T_DIM];
__device__ float  g_p32d[NCODES * DROW];     // lane-duplicated fp32 (shifted bias)
__device__ float  g_p32s[NCODES * PSTRIDE];  // compact padded fp32 (shifted bias)
__device__ double g_p64[NCODES * PDIM];      // exact (unshifted)
__device__ int    g_fix_count;
__device__ int    g_fix_list[NROWS];

// ---------------------------------------------------------------------------
// FFT helpers (radix-4, 4096 = 4^6)
// ---------------------------------------------------------------------------
__device__ __forceinline__ float2 cmul(float2 a, float2 b) {
    return make_float2(fmaf(a.x, b.x, -a.y * b.y), fmaf(a.x, b.y, a.y * b.x));
}

// DIT stages [sstart..5]: digit-reversed input -> natural output.
__device__ void fft4096_r4_dit(float2* __restrict__ buf,
                               const float2* __restrict__ tw, int tid, int sstart) {
    #pragma unroll 1
    for (int s = sstart; s < 6; s++) {
        int quarter = 1 << (2 * s);
        int rstep   = 1024 >> (2 * s);
        #pragma unroll
        for (int q = tid; q < 1024; q += 512) {
            int j   = q & (quarter - 1);
            int grp = q >> (2 * s);
            int pos = grp * (quarter << 2) + j;

            float2 w1 = tw[j * rstep];
            float2 w2 = cmul(w1, w1);
            float2 w3 = cmul(w2, w1);

            float2 a0 = buf[pos];
            float2 a1 = cmul(buf[pos + quarter],     w1);
            float2 a2 = cmul(buf[pos + 2 * quarter], w2);
            float2 a3 = cmul(buf[pos + 3 * quarter], w3);

            float2 t0 = make_float2(a0.x + a2.x, a0.y + a2.y);
            float2 t1 = make_float2(a0.x - a2.x, a0.y - a2.y);
            float2 t2 = make_float2(a1.x + a3.x, a1.y + a3.y);
            float2 t3 = make_float2(a1.x - a3.x, a1.y - a3.y);

            buf[pos]               = make_float2(t0.x + t2.x, t0.y + t2.y);
            buf[pos + quarter]     = make_float2(t1.x + t3.y, t1.y - t3.x);
            buf[pos + 2 * quarter] = make_float2(t0.x - t2.x, t0.y - t2.y);
            buf[pos + 3 * quarter] = make_float2(t1.x - t3.y, t1.y + t3.x);
        }
        __syncthreads();
    }
}

// DIF: natural input -> digit-reversed output.
__device__ void fft4096_r4_dif(float2* __restrict__ buf,
                               const float2* __restrict__ tw, int tid) {
    #pragma unroll 1
    for (int s = 0; s < 6; s++) {
        int quarter = 1024 >> (2 * s);
        int tstep   = 1 << (2 * s);
        int shift   = 10 - 2 * s;
        #pragma unroll
        for (int q = tid; q < 1024; q += 512) {
            int j   = q & (quarter - 1);
            int grp = q >> shift;
            int pos = grp * (quarter << 2) + j;

            float2 a0 = buf[pos];
            float2 a1 = buf[pos + quarter];
            float2 a2 = buf[pos + 2 * quarter];
            float2 a3 = buf[pos + 3 * quarter];

            float2 t0 = make_float2(a0.x + a2.x, a0.y + a2.y);
            float2 t1 = make_float2(a0.x - a2.x, a0.y - a2.y);
            float2 t2 = make_float2(a1.x + a3.x, a1.y + a3.y);
            float2 t3 = make_float2(a1.x - a3.x, a1.y - a3.y);

            float2 b0 = make_float2(t0.x + t2.x, t0.y + t2.y);
            float2 b1 = make_float2(t1.x + t3.y, t1.y - t3.x);
            float2 b2 = make_float2(t0.x - t2.x, t0.y - t2.y);
            float2 b3 = make_float2(t1.x - t3.y, t1.y + t3.x);

            float2 w1 = tw[j * tstep];
            float2 w2 = cmul(w1, w1);
            float2 w3 = cmul(w2, w1);

            buf[pos]               = b0;
            buf[pos + quarter]     = cmul(b1, w1);
            buf[pos + 2 * quarter] = cmul(b2, w2);
            buf[pos + 3 * quarter] = cmul(b3, w3);
        }
        __syncthreads();
    }
}

// ---------------------------------------------------------------------------
// Kernel 1: analytic-signal phase. DIF fwd; Hilbert*conj fused into DIT
// stage 0; DIT stages 1..5; atan2.
// ---------------------------------------------------------------------------
__global__ void phase_kernel(const float* __restrict__ imu) {
    extern __shared__ float2 sm[];
    float2* buf = sm;          // 4096
    float2* tw  = sm + 4096;   // 1024

    int tid = threadIdx.x;
    int bc  = blockIdx.x;      // 0..287

    for (int k = tid; k < 1024; k += 512) {
        float sv, cv;
        sincospif(-(float)k * (1.0f / 2048.0f), &sv, &cv);
        tw[k] = make_float2(cv, sv);
    }

    const float* x = imu + (size_t)bc * T_DIM;
    for (int i = tid; i < 4096; i += 512) {
        buf[i] = make_float2(x[i], 0.0f);
    }
    __syncthreads();

    fft4096_r4_dif(buf, tw, tid);

    // Fused Hilbert + conj + DIT stage 0 (see round 7 derivation)
    for (int g = tid; g < 1024; g += 512) {
        int pos = g * 4;
        float2 x0 = buf[pos];
        float2 x1 = buf[pos + 1];
        float2 a1 = make_float2(2.0f * x1.x, -2.0f * x1.y);
        float2 t0, t1;
        if (g == 0) {
            float2 x2 = buf[2];
            float2 a0 = make_float2(x0.x, -x0.y);
            float2 a2 = make_float2(x2.x, -x2.y);
            t0 = make_float2(a0.x + a2.x, a0.y + a2.y);
            t1 = make_float2(a0.x - a2.x, a0.y - a2.y);
        } else {
            float2 a0 = make_float2(2.0f * x0.x, -2.0f * x0.y);
            t0 = a0;
            t1 = a0;
        }
        buf[pos]     = make_float2(t0.x + a1.x, t0.y + a1.y);
        buf[pos + 1] = make_float2(t1.x + a1.y, t1.y - a1.x);
        buf[pos + 2] = make_float2(t0.x - a1.x, t0.y - a1.y);
        buf[pos + 3] = make_float2(t1.x - a1.y, t1.y + a1.x);
    }
    __syncthreads();

    fft4096_r4_dit(buf, tw, tid, 1);

    float* dst = g_phase_scratch + (size_t)bc * T_DIM;
    for (int i = tid; i < 4096; i += 512) {
        float2 z = buf[i];
        dst[i] = atan2f(-z.y, z.x);
    }
}

// ---------------------------------------------------------------------------
// Kernel 2: precompute per-code projected 12-dim tables
// ---------------------------------------------------------------------------
__device__ __forceinline__ double warp_sum_d(double v) {
    #pragma unroll
    for (int m = 16; m > 0; m >>= 1) v += __shfl_xor_sync(0xFFFFFFFFu, v, m);
    return v;
}

__global__ void precompute_kernel(const float* __restrict__ W_mag,
                                  const float* __restrict__ b_mag,
                                  const float* __restrict__ W_phase,
                                  const float* __restrict__ b_phase,
                                  const float* __restrict__ codebook) {
    int k = blockIdx.x;
    int d = threadIdx.x;     // 0..31
    const float* c = codebook + k * CODE_DIM;

    if (k == 0 && d == 0) g_fix_count = 0;

    double cm = (double)c[d];
    double cp = (double)c[HALF_DIM + d];

    double u[9], v[9];
    #pragma unroll
    for (int i = 0; i < 9; i++) {
        u[i] = (double)W_mag[d * 9 + i] * cm;
        v[i] = (double)W_phase[d * 9 + i] * cp;
    }
    double w = (double)b_mag[d] * cm + (double)b_phase[d] * cp
             - 0.5 * (cm * cm + cp * cp);

    double p[PDIM];
    #pragma unroll
    for (int i = 0; i < 7; i++) p[i] = warp_sum_d(u[i] + v[i]);
    p[7]  = warp_sum_d(u[7]);
    p[8]  = warp_sum_d(u[8]);
    p[9]  = warp_sum_d(v[7]);
    p[10] = warp_sum_d(v[8]);
    p[11] = warp_sum_d(w);

    if (d == 0) {
        #pragma unroll
        for (int i = 0; i < PDIM; i++) {
            g_p64[k * PDIM + i] = p[i];
            float f = (float)p[i];
            if (i == 11) f = (float)(p[i] + (double)SCORE_SHIFT);
            g_p32s[k * PSTRIDE + i] = f;
            g_p32d[k * DROW + i * 2]     = f;
            g_p32d[k * DROW + i * 2 + 1] = f;
        }
    }
}

// ---------------------------------------------------------------------------
// Kernel 3: argmax; 2 rows per thread (f32x2 lanes). ALL lanes of a warp read
// the SAME code row each iteration -> smem broadcast (free). Two 256-code
// sub-loops with separate best regs keep the 8-bit index embed valid.
// Warp-cooperative coalesced output gather.
// ---------------------------------------------------------------------------
__device__ __forceinline__ unsigned long long pack2(float lo, float hi) {
    unsigned long long r;
    asm("mov.b64 %0, {%1, %2};" : "=l"(r) : "f"(lo), "f"(hi));
    return r;
}
__device__ __forceinline__ void unpack2(unsigned long long v, float& lo, float& hi) {
    asm("mov.b64 {%0, %1}, %2;" : "=f"(lo), "=f"(hi) : "l"(v));
}
__device__ __forceinline__ unsigned long long fma2(unsigned long long a,
                                                   unsigned long long b,
                                                   unsigned long long c) {
    unsigned long long d;
    asm("fma.rn.f32x2 %0, %1, %2, %3;" : "=l"(d) : "l"(a), "l"(b), "l"(c));
    return d;
}

__device__ __forceinline__ void load_features(const float* __restrict__ imu,
                                              int row, float* g, float& ph) {
    int b = row >> 12;
    int t = row & 4095;
    const float* phbase = g_phase_scratch + (size_t)(b * C_DIM) * T_DIM + t;
    float s = 0.0f;
    #pragma unroll
    for (int c = 0; c < 9; c++) s += phbase[(size_t)c * T_DIM];
    ph = s * (1.0f / 9.0f);
    const float* ib = imu + (size_t)(b * C_DIM) * T_DIM + t;
    #pragma unroll
    for (int c = 0; c < 9; c++) g[c] = ib[(size_t)c * T_DIM];
    g[9]  = cosf(ph);
    g[10] = sinf(ph);
}

__device__ __forceinline__ float embed8(float s, unsigned ikey) {
    return __uint_as_float((__float_as_uint(s) & 0xFFFFFF00u) | ikey);
}

__global__ void __launch_bounds__(256, 3) quantize_kernel(
    const float* __restrict__ imu,
    const float* __restrict__ codebook,
    float* __restrict__ out) {

    __shared__ __align__(16) float sp[NCODES * DROW];   // 48 KB
    int tid = threadIdx.x;
    {
        const float4* src = (const float4*)g_p32d;
        float4* dst = (float4*)sp;
        for (int i = tid; i < NCODES * DROW / 4; i += 256) dst[i] = src[i];
    }
    __syncthreads();

    int gid = blockIdx.x * 256 + tid;
    int r0 = gid;
    int r1 = gid + NHALF;

    float g0[11], g1[11], ph0, ph1;
    load_features(imu, r0, g0, ph0);
    load_features(imu, r1, g1, ph1);

    unsigned long long gp[11];
    #pragma unroll
    for (int i = 0; i < 11; i++) gp[i] = pack2(g0[i], g1[i]);

    // bests per (half, row)
    float bA0 = -FLT_MAX, b2A0 = -FLT_MAX, bA1 = -FLT_MAX, b2A1 = -FLT_MAX;
    float bB0 = -FLT_MAX, b2B0 = -FLT_MAX, bB1 = -FLT_MAX, b2B1 = -FLT_MAX;

    #pragma unroll 4
    for (int jj = 0; jj < 256; jj++) {
        const ulonglong2* pr = (const ulonglong2*)(sp + jj * DROW);  // broadcast
        ulonglong2 v0 = pr[0], v1 = pr[1], v2 = pr[2];
        ulonglong2 v3 = pr[3], v4 = pr[4], v5 = pr[5];
        unsigned long long acc = v5.y;
        acc = fma2(gp[0],  v0.x, acc);
        acc = fma2(gp[1],  v0.y, acc);
        acc = fma2(gp[2],  v1.x, acc);
        acc = fma2(gp[3],  v1.y, acc);
        acc = fma2(gp[4],  v2.x, acc);
        acc = fma2(gp[5],  v2.y, acc);
        acc = fma2(gp[6],  v3.x, acc);
        acc = fma2(gp[7],  v3.y, acc);
        acc = fma2(gp[8],  v4.x, acc);
        acc = fma2(gp[9],  v4.y, acc);
        acc = fma2(gp[10], v5.x, acc);
        float s0, s1;
        unpack2(acc, s0, s1);
        unsigned ikey = 255u - (unsigned)jj;
        float e0 = embed8(s0, ikey);
        float e1 = embed8(s1, ikey);
        b2A0 = fmaxf(b2A0, fminf(e0, bA0));  bA0 = fmaxf(bA0, e0);
        b2A1 = fmaxf(b2A1, fminf(e1, bA1));  bA1 = fmaxf(bA1, e1);
    }
    #pragma unroll 4
    for (int jj = 0; jj < 256; jj++) {
        const ulonglong2* pr = (const ulonglong2*)(sp + (256 + jj) * DROW);
        ulonglong2 v0 = pr[0], v1 = pr[1], v2 = pr[2];
        ulonglong2 v3 = pr[3], v4 = pr[4], v5 = pr[5];
        unsigned long long acc = v5.y;
        acc = fma2(gp[0],  v0.x, acc);
        acc = fma2(gp[1],  v0.y, acc);
        acc = fma2(gp[2],  v1.x, acc);
        acc = fma2(gp[3],  v1.y, acc);
        acc = fma2(gp[4],  v2.x, acc);
        acc = fma2(gp[5],  v2.y, acc);
        acc = fma2(gp[6],  v3.x, acc);
        acc = fma2(gp[7],  v3.y, acc);
        acc = fma2(gp[8],  v4.x, acc);
        acc = fma2(gp[9],  v4.y, acc);
        acc = fma2(gp[10], v5.x, acc);
        float s0, s1;
        unpack2(acc, s0, s1);
        unsigned ikey = 255u - (unsigned)jj;
        float e0 = embed8(s0, ikey);
        float e1 = embed8(s1, ikey);
        b2B0 = fmaxf(b2B0, fminf(e0, bB0));  bB0 = fmaxf(bB0, e0);
        b2B1 = fmaxf(b2B1, fminf(e1, bB1));  bB1 = fmaxf(bB1, e1);
    }

    // merge halves (A preferred on equal embedded value -> lower index)
    float m0  = fmaxf(bA0, bB0);
    float m20 = fmaxf(fminf(bA0, bB0), fmaxf(b2A0, b2B0));
    int bidx0 = (bA0 >= bB0)
              ? (255 - (int)(__float_as_uint(bA0) & 255u))
              : (511 - (int)(__float_as_uint(bB0) & 255u));
    float m1  = fmaxf(bA1, bB1);
    float m21 = fmaxf(fminf(bA1, bB1), fmaxf(b2A1, b2B1));
    int bidx1 = (bA1 >= bB1)
              ? (255 - (int)(__float_as_uint(bA1) & 255u))
              : (511 - (int)(__float_as_uint(bB1) & 255u));

    out[IDX_OFF + r0] = (float)bidx0;
    out[IDX_OFF + r1] = (float)bidx1;
    out[PH_OFF + r0] = ph0;
    out[PH_OFF + r1] = ph1;
    if (m0 - m20 < FIX_THR) {
        int slot = atomicAdd(&g_fix_count, 1);
        g_fix_list[slot] = r0;
    }
    if (m1 - m21 < FIX_THR) {
        int slot = atomicAdd(&g_fix_count, 1);
        g_fix_list[slot] = r1;
    }

    // Warp-cooperative coalesced gather: warp's rows are contiguous.
    int lane = tid & 31;
    int wrow0 = gid & ~31;              // first row of warp's region 0
    const float4* cb4 = (const float4*)codebook;
    float4* o4 = (float4*)out;
    #pragma unroll
    for (int i = 0; i < 16; i++) {
        int f = i * 32 + lane;          // 0..511 float4s in warp region
        int rsel = f >> 4;              // row-within-warp 0..31
        int col  = f & 15;
        int bs0 = __shfl_sync(0xFFFFFFFFu, bidx0, rsel);
        o4[(size_t)(wrow0 + rsel) * 16 + col] = cb4[bs0 * 16 + col];
    }
    int wrow1 = wrow0 + NHALF;
    #pragma unroll
    for (int i = 0; i < 16; i++) {
        int f = i * 32 + lane;
        int rsel = f >> 4;
        int col  = f & 15;
        int bs1 = __shfl_sync(0xFFFFFFFFu, bidx1, rsel);
        o4[(size_t)(wrow1 + rsel) * 16 + col] = cb4[bs1 * 16 + col];
    }
}

// ---------------------------------------------------------------------------
// Kernel 4: exact rerank for flagged rows (unchanged logic + early exit).
// ---------------------------------------------------------------------------
__global__ void __launch_bounds__(256) fixup_kernel(
    const float* __restrict__ imu,
    const float* __restrict__ codebook,
    float* __restrict__ out) {

    int n = g_fix_count;
    if (blockIdx.x * 8 >= n) return;    // this block's warps have no rows

    __shared__ float st[NCODES * PSTRIDE];   // 26 KB
    int tid = threadIdx.x;
    for (int i = tid; i < NCODES * PSTRIDE; i += 256) st[i] = g_p32s[i];
    __syncthreads();

    int lane = tid & 31;
    int warp = (blockIdx.x * blockDim.x + tid) >> 5;
    int nwarps = (gridDim.x * blockDim.x) >> 5;

    for (int i = warp; i < n; i += nwarps) {
        int row = g_fix_list[i];
        float gf[11], ph;
        load_features(imu, row, gf, ph);

        // pass 1: fp32 scores from smem
        float sc[16];
        float lbest = -FLT_MAX;
        #pragma unroll
        for (int c = 0; c < 16; c++) {
            const float* pr = st + (c * 32 + lane) * PSTRIDE;
            float s = pr[11];
            #pragma unroll
            for (int k = 0; k < 11; k++) s = fmaf(gf[k], pr[k], s);
            sc[c] = s;
            lbest = fmaxf(lbest, s);
        }
        #pragma unroll
        for (int m = 16; m > 0; m >>= 1)
            lbest = fmaxf(lbest, __shfl_xor_sync(0xFFFFFFFFu, lbest, m));
        float thr = lbest - 1e-3f;

        // pass 2: fp64 for candidates only
        double gd[11];
        #pragma unroll
        for (int k = 0; k < 11; k++) gd[k] = (double)gf[k];
        double bd = -1.0e300;
        int bi = NCODES;
        #pragma unroll 1
        for (int c = 0; c < 16; c++) {
            if (sc[c] >= thr) {
                int j = c * 32 + lane;
                const double* pr = g_p64 + j * PDIM;
                double s0 = pr[11];
                double s1 = 0.0;
                #pragma unroll
                for (int k = 0; k < 10; k += 2) {
                    s0 += gd[k]     * pr[k];
                    s1 += gd[k + 1] * pr[k + 1];
                }
                s0 += gd[10] * pr[10];
                double s = s0 + s1;
                if (s > bd || (s == bd && j < bi)) { bd = s; bi = j; }
            }
        }
        #pragma unroll
        for (int m = 16; m > 0; m >>= 1) {
            double od = __shfl_xor_sync(0xFFFFFFFFu, bd, m);
            int    oi = __shfl_xor_sync(0xFFFFFFFFu, bi, m);
            if (od > bd || (od == bd && oi < bi)) { bd = od; bi = oi; }
        }
        if (lane == 0) out[IDX_OFF + row] = (float)bi;
        if (lane < 16) {
            const float4* cb = (const float4*)(codebook + (size_t)bi * CODE_DIM);
            float4* oq = (float4*)(out + (size_t)row * CODE_DIM);
            oq[lane] = cb[lane];
        }
    }
}

// ---------------------------------------------------------------------------
extern "C" void kernel_launch(void* const* d_in, const int* in_sizes, int n_in,
                              void* d_out, int out_size) {
    const float* imu      = (const float*)d_in[0];
    const float* W_mag    = (const float*)d_in[1];
    const float* b_mag    = (const float*)d_in[2];
    const float* W_phase  = (const float*)d_in[3];
    const float* b_phase  = (const float*)d_in[4];
    const float* codebook = (const float*)d_in[5];
    float* out = (float*)d_out;

    phase_kernel<<<B_DIM * C_DIM, 512, 5120 * sizeof(float2)>>>(imu);
    precompute_kernel<<<NCODES, 32>>>(W_mag, b_mag, W_phase, b_phase, codebook);
    quantize_kernel<<<NHALF / 256, 256>>>(imu, codebook, out);
    fixup_kernel<<<296, 256>>>(imu, codebook, out);
}